// round 8
// baseline (speedup 1.0000x reference)
#include <cuda_runtime.h>
#include <cuda_bf16.h>
#include <math.h>
#include <stdint.h>

// Problem dims
#define B 128
#define D 512
#define S 512
#define F 1024     // 2*D
#define TOPK 10

// scratch (device globals: allocation-free)
__device__ float g_info[B * D];
__device__ float g_gproj[B * D];
__device__ float g_spe[S * D];
__device__ float g_part[4][B * S];   // partial scores per 128-col chunk

// bf16 3-way splits of feat (A operand) and W1a^T (B operand, [d][f] n-major)
__device__ __nv_bfloat16 g_as0[B * S * D];
__device__ __nv_bfloat16 g_as1[B * S * D];
__device__ __nv_bfloat16 g_as2[B * S * D];
__device__ __nv_bfloat16 g_w1t0[D * D];
__device__ __nv_bfloat16 g_w1t1[D * D];
__device__ __nv_bfloat16 g_w1t2[D * D];

// ---------------- helpers ----------------
__device__ __forceinline__ uint32_t smem_u32(const void* p) {
    uint32_t a;
    asm("{ .reg .u64 t; cvta.to.shared.u64 t, %1; cvt.u32.u64 %0, t; }" : "=r"(a) : "l"(p));
    return a;
}
#define CP_ASYNC16(dst, src) \
    asm volatile("cp.async.cg.shared.global [%0], [%1], 16;" :: "r"(dst), "l"(src))

#define LDSM4(r, addr) \
    asm volatile("ldmatrix.sync.aligned.m8n8.x4.shared.b16 {%0,%1,%2,%3}, [%4];" \
        : "=r"((r)[0]), "=r"((r)[1]), "=r"((r)[2]), "=r"((r)[3]) : "r"(addr))

#define MMA_BF16(d, a, b0r, b1r) \
    asm volatile("mma.sync.aligned.m16n8k16.row.col.f32.bf16.bf16.f32 " \
        "{%0,%1,%2,%3}, {%4,%5,%6,%7}, {%8,%9}, {%0,%1,%2,%3};" \
        : "+f"((d)[0]), "+f"((d)[1]), "+f"((d)[2]), "+f"((d)[3]) \
        : "r"((a)[0]), "r"((a)[1]), "r"((a)[2]), "r"((a)[3]), "r"(b0r), "r"(b1r))

// split fp32 -> 3 bf16 terms
__device__ __forceinline__ void split3(float a, __nv_bfloat16& h0, __nv_bfloat16& h1, __nv_bfloat16& h2) {
    h0 = __float2bfloat16(a);
    float r1 = a - __bfloat162float(h0);
    h1 = __float2bfloat16(r1);
    float r2 = r1 - __bfloat162float(h1);
    h2 = __float2bfloat16(r2);
}

// ---------------------------------------------------------------------------
// Kernel 1: row means of x
__global__ void k_mean(const float* __restrict__ x) {
    int row = blockIdx.x * 8 + (threadIdx.x >> 5);
    int lane = threadIdx.x & 31;
    const float4* p = (const float4*)(x + (size_t)row * S);
    float s = 0.f;
    #pragma unroll
    for (int i = lane; i < S / 4; i += 32) {
        float4 v = p[i];
        s += v.x + v.y + v.z + v.w;
    }
    #pragma unroll
    for (int o = 16; o; o >>= 1) s += __shfl_xor_sync(0xffffffffu, s, o);
    if (lane == 0) g_info[row] = s * (1.0f / (float)S);
}

// ---------------------------------------------------------------------------
// Kernel 2: feat[b,s,d] = x[b,d,s]; also emit 3-way bf16 splits of feat
__global__ void k_transpose(const float* __restrict__ x, float* __restrict__ feat) {
    __shared__ float tile[32][33];
    int b = blockIdx.z;
    int d0 = blockIdx.y * 32, s0 = blockIdx.x * 32;
    const float* xb = x + (size_t)b * D * S;
    float* fb = feat + (size_t)b * S * D;
    int tx = threadIdx.x;
    #pragma unroll
    for (int i = threadIdx.y; i < 32; i += 8)
        tile[i][tx] = xb[(size_t)(d0 + i) * S + s0 + tx];
    __syncthreads();
    #pragma unroll
    for (int i = threadIdx.y; i < 32; i += 8) {
        float a = tile[tx][i];
        size_t o = (size_t)b * S * D + (size_t)(s0 + i) * D + d0 + tx;
        fb[(size_t)(s0 + i) * D + d0 + tx] = a;
        __nv_bfloat16 h0, h1, h2;
        split3(a, h0, h1, h2);
        g_as0[o] = h0; g_as1[o] = h1; g_as2[o] = h2;
    }
}

// ---------------------------------------------------------------------------
// Kernel 2b: w1t[d][f] = w1[f][d] (first D rows = W1a), 3-way bf16 split
__global__ void k_w1t(const float* __restrict__ w1) {
    __shared__ float tile[32][33];
    int f0 = blockIdx.y * 32, d0 = blockIdx.x * 32;
    int tx = threadIdx.x;
    #pragma unroll
    for (int i = threadIdx.y; i < 32; i += 8)
        tile[i][tx] = w1[(size_t)(f0 + i) * D + d0 + tx];
    __syncthreads();
    #pragma unroll
    for (int i = threadIdx.y; i < 32; i += 8) {
        float a = tile[tx][i];  // = w1[f0+tx][d0+i]
        size_t o = (size_t)(d0 + i) * D + f0 + tx;
        __nv_bfloat16 h0, h1, h2;
        split3(a, h0, h1, h2);
        g_w1t0[o] = h0; g_w1t1[o] = h1; g_w1t2[o] = h2;
    }
}

// ---------------------------------------------------------------------------
// Kernel 3: spe[s,d] = sum_f pe[s,f]*w1[f,d] + b1[d]
#define SPE_ROWS 16
__global__ void k_spe(const float* __restrict__ w1, const float* __restrict__ b1) {
    __shared__ float pes[128][SPE_ROWS];
    int tid = threadIdx.x;
    int s0 = (blockIdx.x >> 2) * SPE_ROWS;
    int d0 = (blockIdx.x & 3) * 128;
    int rg = tid >> 7;
    int dc = tid & 127;
    int d = d0 + dc;
    float acc[8] = {};

    for (int f0 = 0; f0 < F; f0 += 128) {
        __syncthreads();
        for (int v = tid; v < 128 * SPE_ROWS; v += 256) {
            int fc = v >> 4, r = v & 15;
            int f = f0 + fc;
            int fe = f & ~1;
            float div = expf(-9.210340371976184f * (float)fe / (float)F);
            float ang = (float)(s0 + r) * div;
            pes[fc][r] = (f & 1) ? cosf(ang) : sinf(ang);
        }
        __syncthreads();
        #pragma unroll 4
        for (int fc = 0; fc < 128; fc++) {
            float w = w1[(size_t)(f0 + fc) * D + d];
            #pragma unroll
            for (int r = 0; r < 8; r++)
                acc[r] += pes[fc][rg * 8 + r] * w;
        }
    }
    float bv = b1[d];
    #pragma unroll
    for (int r = 0; r < 8; r++)
        g_spe[(size_t)(s0 + rg * 8 + r) * D + d] = acc[r] + bv;
}

// ---------------------------------------------------------------------------
// Kernel 4: g_proj[b,d] = sum_f info_g[b,f] * w1[D+f, d]
// grid 512 (b x 4 d-chunks); 2 f-groups x 128 d per block, smem reduce.
__global__ void k_gproj(const float* __restrict__ w1) {
    __shared__ float info_s[D];
    __shared__ float part[128];
    int tid = threadIdx.x;
    int b = blockIdx.x >> 2, dq = blockIdx.x & 3;
    info_s[tid] = g_info[b * D + tid];
    info_s[tid + 256] = g_info[b * D + tid + 256];
    __syncthreads();
    int fg = tid >> 7, dc = tid & 127;
    int d = dq * 128 + dc;
    const float* wb = w1 + (size_t)D * D + d;
    int fb = fg * 256;
    float a0 = 0.f, a1 = 0.f, a2 = 0.f, a3 = 0.f;
    #pragma unroll 4
    for (int f = 0; f < 256; f += 4) {
        a0 += info_s[fb + f]     * wb[(size_t)(fb + f) * D];
        a1 += info_s[fb + f + 1] * wb[(size_t)(fb + f + 1) * D];
        a2 += info_s[fb + f + 2] * wb[(size_t)(fb + f + 2) * D];
        a3 += info_s[fb + f + 3] * wb[(size_t)(fb + f + 3) * D];
    }
    float s = (a0 + a1) + (a2 + a3);
    if (fg == 1) part[dc] = s;
    __syncthreads();
    if (fg == 0) g_gproj[b * D + d] = s + part[dc];
}

// ---------------------------------------------------------------------------
// Kernel 5: bf16 mma.sync GEMM, fp32 via 3-way split / 6 products (i+j<=2).
// Block: M=128 s-rows x N=128 d-cols, K=512, Kc=32, double-buffered cp.async.
// 8 warps as 2(M) x 4(N); warp tile 64x32; mma m16n8k16.
// smem rows padded to 80B -> conflict-free LDSM.
#define PITCH 10240                      // 128 rows * 80 B per (split) tile
#define ABUF(buf, sp) (((buf) * 3 + (sp)) * PITCH)
#define BBUF(buf, sp) (61440 + ((buf) * 3 + (sp)) * PITCH)
#define SMEM_GEMM 122880

__global__ __launch_bounds__(256, 1) void k_gemm_mma(const float* __restrict__ w2v) {
    extern __shared__ __align__(16) char smem[];
    uint32_t sb = smem_u32(smem);
    int tid = threadIdx.x, wid = tid >> 5, lane = tid & 31;
    int bidx = blockIdx.x >> 4;                 // batch
    int st = (blockIdx.x >> 2) & 3;             // s-tile (128 rows)
    int nc = blockIdx.x & 3;                    // n-chunk (128 cols)
    int s0 = st * 128, n0 = nc * 128;
    int mw = wid & 1, nw = wid >> 1;            // 2 x 4 warp grid

    const __nv_bfloat16* aptr[3] = {g_as0, g_as1, g_as2};
    const __nv_bfloat16* bptr[3] = {g_w1t0, g_w1t1, g_w1t2};
    size_t arow0 = (size_t)(bidx * S + s0);
    size_t brow0 = (size_t)n0;

    float acc[4][4][4];
    #pragma unroll
    for (int i = 0; i < 4; i++)
        #pragma unroll
        for (int j = 0; j < 4; j++)
            #pragma unroll
            for (int e = 0; e < 4; e++) acc[i][j][e] = 0.f;

#define LOAD_CHUNK(f0, bufi) do {                                              \
    for (int t = tid; t < 1536; t += 256) {                                    \
        int sp = t >> 9; int rem = t & 511; int row = rem >> 2; int ck = rem & 3; \
        CP_ASYNC16(sb + ABUF(bufi, sp) + row * 80 + ck * 16,                   \
                   aptr[sp] + (arow0 + row) * D + (f0) + ck * 8);              \
        CP_ASYNC16(sb + BBUF(bufi, sp) + row * 80 + ck * 16,                   \
                   bptr[sp] + (brow0 + row) * D + (f0) + ck * 8);              \
    }                                                                          \
    asm volatile("cp.async.commit_group;");                                    \
} while (0)

    LOAD_CHUNK(0, 0);
    int buf = 0;

    for (int c = 0; c < 16; c++) {
        if (c < 15) {
            LOAD_CHUNK((c + 1) * 32, buf ^ 1);
            asm volatile("cp.async.wait_group 1;");
        } else {
            asm volatile("cp.async.wait_group 0;");
        }
        __syncthreads();

        #pragma unroll
        for (int k16 = 0; k16 < 2; k16++) {
            // B fragments for all 3 splits, 2 nt-pairs each
            uint32_t bf[3][2][4];
            int brow = nw * 32 + ((lane >> 4) & 1) * 8 + (lane & 7);
            int bko = ((lane >> 3) & 1) * 16 + k16 * 32;
            #pragma unroll
            for (int sp = 0; sp < 3; sp++)
                #pragma unroll
                for (int q = 0; q < 2; q++)
                    LDSM4(bf[sp][q], sb + BBUF(buf, sp) + (brow + q * 16) * 80 + bko);

            int amrow = mw * 64 + (lane & 15);
            int ako = (lane >> 4) * 16 + k16 * 32;
            #pragma unroll
            for (int i = 0; i < 3; i++) {
                uint32_t af[4][4];
                #pragma unroll
                for (int mt = 0; mt < 4; mt++)
                    LDSM4(af[mt], sb + ABUF(buf, i) + (amrow + mt * 16) * 80 + ako);
                #pragma unroll
                for (int j = 0; j < 3; j++) {
                    if (i + j > 2) continue;
                    #pragma unroll
                    for (int mt = 0; mt < 4; mt++) {
                        MMA_BF16(acc[mt][0], af[mt], bf[j][0][0], bf[j][0][1]);
                        MMA_BF16(acc[mt][1], af[mt], bf[j][0][2], bf[j][0][3]);
                        MMA_BF16(acc[mt][2], af[mt], bf[j][1][0], bf[j][1][1]);
                        MMA_BF16(acc[mt][3], af[mt], bf[j][1][2], bf[j][1][3]);
                    }
                }
            }
        }
        __syncthreads();
        buf ^= 1;
    }

    // ---- epilogue: v += spe + gproj; relu; dot w2 -> partial scores ----
    float* scp = (float*)smem;   // reuse smem: 128 rows x 4 nw
    int g = lane >> 2, tig = lane & 3;
    const float* gp = g_gproj + bidx * D;
    #pragma unroll
    for (int mt = 0; mt < 4; mt++) {
        int rl0 = mw * 64 + mt * 16 + g;
        int sg0 = s0 + rl0;
        float p0 = 0.f, p1 = 0.f;
        #pragma unroll
        for (int nt = 0; nt < 4; nt++) {
            #pragma unroll
            for (int e = 0; e < 2; e++) {
                int dcol = n0 + nw * 32 + nt * 8 + tig * 2 + e;
                float gpw = __ldg(&gp[dcol]);
                float wv  = __ldg(&w2v[dcol]);
                float v0 = acc[mt][nt][e]     + __ldg(&g_spe[(size_t)sg0 * D + dcol])       + gpw;
                float v1 = acc[mt][nt][2 + e] + __ldg(&g_spe[(size_t)(sg0 + 8) * D + dcol]) + gpw;
                if (v0 > 0.f) p0 += v0 * wv;
                if (v1 > 0.f) p1 += v1 * wv;
            }
        }
        p0 += __shfl_xor_sync(0xffffffffu, p0, 1);
        p0 += __shfl_xor_sync(0xffffffffu, p0, 2);
        p1 += __shfl_xor_sync(0xffffffffu, p1, 1);
        p1 += __shfl_xor_sync(0xffffffffu, p1, 2);
        if (tig == 0) {
            scp[rl0 * 4 + nw] = p0;
            scp[(rl0 + 8) * 4 + nw] = p1;
        }
    }
    __syncthreads();
    if (tid < 128)
        g_part[nc][bidx * S + s0 + tid] =
            (scp[tid * 4] + scp[tid * 4 + 1]) + (scp[tid * 4 + 2] + scp[tid * 4 + 3]);
}

// ---------------------------------------------------------------------------
// Kernel 6: sum partials, per-batch top-10, sort ascending, one-hot + gather.
__global__ void k_topk(float* __restrict__ out, const float* __restrict__ feat) {
    __shared__ float sv[S];
    __shared__ float rv[S];
    __shared__ int ri[S];
    __shared__ int sel[TOPK];
    int b = blockIdx.x;
    int t = threadIdx.x;
    int o = b * S + t;

    sv[t] = (g_part[0][o] + g_part[1][o]) + (g_part[2][o] + g_part[3][o]);

    for (int k = 0; k < TOPK; k++) {
        __syncthreads();
        rv[t] = sv[t];
        ri[t] = t;
        __syncthreads();
        for (int str = 256; str > 0; str >>= 1) {
            if (t < str) {
                float v2 = rv[t + str];
                int i2 = ri[t + str];
                if (v2 > rv[t] || (v2 == rv[t] && i2 < ri[t])) { rv[t] = v2; ri[t] = i2; }
            }
            __syncthreads();
        }
        if (t == 0) {
            sel[k] = ri[0];
            sv[ri[0]] = -INFINITY;
        }
    }
    __syncthreads();
    if (t == 0) {
        for (int i = 1; i < TOPK; i++) {
            int v = sel[i], j = i - 1;
            while (j >= 0 && sel[j] > v) { sel[j + 1] = sel[j]; j--; }
            sel[j + 1] = v;
        }
    }
    __syncthreads();

    float* oi = out + (size_t)b * TOPK * S;
    for (int i = t; i < TOPK * S; i += 512) {
        int k = i >> 9, s = i & (S - 1);
        oi[i] = (s == sel[k]) ? 1.0f : 0.0f;
    }
    float* os = out + (size_t)B * TOPK * S + (size_t)b * TOPK * D;
    const float* fb = feat + (size_t)b * S * D;
    for (int i = t; i < TOPK * D; i += 512) {
        int k = i >> 9, d = i & (D - 1);
        os[i] = fb[(size_t)sel[k] * D + d];
    }
}

// ---------------------------------------------------------------------------
extern "C" void kernel_launch(void* const* d_in, const int* in_sizes, int n_in,
                              void* d_out, int out_size) {
    (void)in_sizes; (void)n_in; (void)out_size;
    const float* x  = (const float*)d_in[0];
    const float* w1 = (const float*)d_in[1];
    const float* b1 = (const float*)d_in[2];
    const float* w2 = (const float*)d_in[3];
    // d_in[4] = b2: constant shift, does not affect top-k ordering -> unused.

    float* out = (float*)d_out;
    float* feat = out + (size_t)B * TOPK * S + (size_t)B * TOPK * D;

    cudaFuncSetAttribute(k_gemm_mma, cudaFuncAttributeMaxDynamicSharedMemorySize, SMEM_GEMM);

    k_mean<<<(B * D) / 8, 256>>>(x);
    k_transpose<<<dim3(S / 32, D / 32, B), dim3(32, 8)>>>(x, feat);
    k_w1t<<<dim3(16, 16), dim3(32, 8)>>>(w1);
    k_spe<<<(S / SPE_ROWS) * 4, 256>>>(w1, b1);
    k_gproj<<<512, 256>>>(w1);
    k_gemm_mma<<<B * 4 * 4, 256, SMEM_GEMM>>>(w2);
    k_topk<<<B, 512>>>(out, feat);
}

// round 11
// speedup vs baseline: 1.2032x; 1.2032x over previous
#include <cuda_runtime.h>
#include <cuda_bf16.h>
#include <math.h>
#include <stdint.h>

// Problem dims
#define B 128
#define D 512
#define S 512
#define F 1024     // 2*D
#define TOPK 10

// scratch (device globals: allocation-free)
__device__ float g_info[B * D];
__device__ float g_gproj[B * D];
__device__ float g_spe[S * D];
__device__ float g_spe_part[8][S * D];
__device__ float g_part[4][B * S];   // partial scores per 128-col chunk

// bf16 3-way splits of feat (A), W1a^T / W1b^T (B, [d][f] k-contig), pe
__device__ __nv_bfloat16 g_as0[B * S * D];
__device__ __nv_bfloat16 g_as1[B * S * D];
__device__ __nv_bfloat16 g_as2[B * S * D];
__device__ __nv_bfloat16 g_w1t0[D * D];
__device__ __nv_bfloat16 g_w1t1[D * D];
__device__ __nv_bfloat16 g_w1t2[D * D];
__device__ __nv_bfloat16 g_w1bt0[D * D];
__device__ __nv_bfloat16 g_w1bt1[D * D];
__device__ __nv_bfloat16 g_w1bt2[D * D];
__device__ __nv_bfloat16 g_pe0[S * F];
__device__ __nv_bfloat16 g_pe1[S * F];
__device__ __nv_bfloat16 g_pe2[S * F];

// ---------------- helpers ----------------
__device__ __forceinline__ uint32_t smem_u32(const void* p) {
    uint32_t a;
    asm("{ .reg .u64 t; cvta.to.shared.u64 t, %1; cvt.u32.u64 %0, t; }" : "=r"(a) : "l"(p));
    return a;
}
#define CP_ASYNC16(dst, src) \
    asm volatile("cp.async.cg.shared.global [%0], [%1], 16;" :: "r"(dst), "l"(src))

#define LDSM4(r, addr) \
    asm volatile("ldmatrix.sync.aligned.m8n8.x4.shared.b16 {%0,%1,%2,%3}, [%4];" \
        : "=r"((r)[0]), "=r"((r)[1]), "=r"((r)[2]), "=r"((r)[3]) : "r"(addr))

#define MMA_BF16(d, a, b0r, b1r) \
    asm volatile("mma.sync.aligned.m16n8k16.row.col.f32.bf16.bf16.f32 " \
        "{%0,%1,%2,%3}, {%4,%5,%6,%7}, {%8,%9}, {%0,%1,%2,%3};" \
        : "+f"((d)[0]), "+f"((d)[1]), "+f"((d)[2]), "+f"((d)[3]) \
        : "r"((a)[0]), "r"((a)[1]), "r"((a)[2]), "r"((a)[3]), "r"(b0r), "r"(b1r))

// split fp32 -> 3 bf16 terms
__device__ __forceinline__ void split3(float a, __nv_bfloat16& h0, __nv_bfloat16& h1, __nv_bfloat16& h2) {
    h0 = __float2bfloat16(a);
    float r1 = a - __bfloat162float(h0);
    h1 = __float2bfloat16(r1);
    float r2 = r1 - __bfloat162float(h1);
    h2 = __float2bfloat16(r2);
}

// ---------------------------------------------------------------------------
// Kernel 1: row means of x
__global__ void k_mean(const float* __restrict__ x) {
    int row = blockIdx.x * 8 + (threadIdx.x >> 5);
    int lane = threadIdx.x & 31;
    const float4* p = (const float4*)(x + (size_t)row * S);
    float s = 0.f;
    #pragma unroll
    for (int i = lane; i < S / 4; i += 32) {
        float4 v = p[i];
        s += v.x + v.y + v.z + v.w;
    }
    #pragma unroll
    for (int o = 16; o; o >>= 1) s += __shfl_xor_sync(0xffffffffu, s, o);
    if (lane == 0) g_info[row] = s * (1.0f / (float)S);
}

// ---------------------------------------------------------------------------
// Kernel 2: feat[b,s,d] = x[b,d,s]; also emit 3-way bf16 splits of feat
__global__ void k_transpose(const float* __restrict__ x, float* __restrict__ feat) {
    __shared__ float tile[32][33];
    int b = blockIdx.z;
    int d0 = blockIdx.y * 32, s0 = blockIdx.x * 32;
    const float* xb = x + (size_t)b * D * S;
    float* fb = feat + (size_t)b * S * D;
    int tx = threadIdx.x;
    #pragma unroll
    for (int i = threadIdx.y; i < 32; i += 8)
        tile[i][tx] = xb[(size_t)(d0 + i) * S + s0 + tx];
    __syncthreads();
    #pragma unroll
    for (int i = threadIdx.y; i < 32; i += 8) {
        float a = tile[tx][i];
        size_t o = (size_t)b * S * D + (size_t)(s0 + i) * D + d0 + tx;
        fb[(size_t)(s0 + i) * D + d0 + tx] = a;
        __nv_bfloat16 h0, h1, h2;
        split3(a, h0, h1, h2);
        g_as0[o] = h0; g_as1[o] = h1; g_as2[o] = h2;
    }
}

// ---------------------------------------------------------------------------
// Kernel 2b: transpose+split all of w1: [d][f] for f<512 -> w1t, f>=512 -> w1bt
__global__ void k_w1t(const float* __restrict__ w1) {
    __shared__ float tile[32][33];
    int f0 = blockIdx.y * 32, d0 = blockIdx.x * 32;
    int tx = threadIdx.x;
    #pragma unroll
    for (int i = threadIdx.y; i < 32; i += 8)
        tile[i][tx] = w1[(size_t)(f0 + i) * D + d0 + tx];
    __syncthreads();
    int hi = (f0 >= 512);
    __nv_bfloat16* o0 = hi ? g_w1bt0 : g_w1t0;
    __nv_bfloat16* o1 = hi ? g_w1bt1 : g_w1t1;
    __nv_bfloat16* o2 = hi ? g_w1bt2 : g_w1t2;
    int fb = f0 - hi * 512;
    #pragma unroll
    for (int i = threadIdx.y; i < 32; i += 8) {
        float a = tile[tx][i];  // = w1[f0+tx][d0+i]
        size_t o = (size_t)(d0 + i) * D + fb + tx;
        __nv_bfloat16 h0, h1, h2;
        split3(a, h0, h1, h2);
        o0[o] = h0; o1[o] = h1; o2[o] = h2;
    }
}

// ---------------------------------------------------------------------------
// Kernel 2c: pe[s][f] sinusoid, 3-way bf16 split
__global__ void k_pe() {
    int idx = blockIdx.x * 256 + threadIdx.x;
    int s = idx >> 10, f = idx & 1023;
    int fe = f & ~1;
    float div = expf(-9.210340371976184f * (float)fe / (float)F);
    float ang = (float)s * div;
    float v = (f & 1) ? cosf(ang) : sinf(ang);
    __nv_bfloat16 h0, h1, h2;
    split3(v, h0, h1, h2);
    g_pe0[idx] = h0; g_pe1[idx] = h1; g_pe2[idx] = h2;
}

// ---------------------------------------------------------------------------
// Kernel 4: g_proj[b,d] = sum_f info_g[b,f] * w1[D+f, d]
__global__ void k_gproj(const float* __restrict__ w1) {
    __shared__ float info_s[D];
    __shared__ float part[128];
    int tid = threadIdx.x;
    int b = blockIdx.x >> 2, dq = blockIdx.x & 3;
    info_s[tid] = g_info[b * D + tid];
    info_s[tid + 256] = g_info[b * D + tid + 256];
    __syncthreads();
    int fg = tid >> 7, dc = tid & 127;
    int d = dq * 128 + dc;
    const float* wb = w1 + (size_t)D * D + d;
    int fb = fg * 256;
    float a0 = 0.f, a1 = 0.f, a2 = 0.f, a3 = 0.f;
    #pragma unroll 4
    for (int f = 0; f < 256; f += 4) {
        a0 += info_s[fb + f]     * wb[(size_t)(fb + f) * D];
        a1 += info_s[fb + f + 1] * wb[(size_t)(fb + f + 1) * D];
        a2 += info_s[fb + f + 2] * wb[(size_t)(fb + f + 2) * D];
        a3 += info_s[fb + f + 3] * wb[(size_t)(fb + f + 3) * D];
    }
    float s = (a0 + a1) + (a2 + a3);
    if (fg == 1) part[dc] = s;
    __syncthreads();
    if (fg == 0) g_gproj[b * D + d] = s + part[dc];
}

// ---------------------------------------------------------------------------
// Shared GEMM tile layout (pitch 80B, Kc=32, double buffered)
#define PITCH 10240                      // 128 rows * 80 B per (split) tile
#define ABUF(buf, sp) (((buf) * 3 + (sp)) * PITCH)
#define BBUF(buf, sp) (61440 + ((buf) * 3 + (sp)) * PITCH)
#define SMEM_GEMM 122880

// ---------------------------------------------------------------------------
// Kernel 3: spe via HMMA: spe_part[ks] = pe[:, ks*128:(ks+1)*128] @ W1[ks-chunk]
// grid = 8(ks) x 4(st) x 4(nc) = 128 blocks; per block K=128 (4 chunks of 32).
__global__ __launch_bounds__(256, 1) void k_spe_mma() {
    extern __shared__ __align__(16) char smem[];
    uint32_t sb = smem_u32(smem);
    int tid = threadIdx.x, wid = tid >> 5, lane = tid & 31;
    int ks = blockIdx.x >> 4;
    int st = (blockIdx.x >> 2) & 3;
    int nc = blockIdx.x & 3;
    int s0 = st * 128, n0 = nc * 128;
    int mw = wid & 1, nw = wid >> 1;

    const __nv_bfloat16* apz[3] = {g_pe0, g_pe1, g_pe2};
    const __nv_bfloat16* bpz[3];
    int f0base = ks * 128;
    int fob;
    if (ks < 4) { bpz[0] = g_w1t0;  bpz[1] = g_w1t1;  bpz[2] = g_w1t2;  fob = f0base; }
    else        { bpz[0] = g_w1bt0; bpz[1] = g_w1bt1; bpz[2] = g_w1bt2; fob = f0base - 512; }

    float acc[4][4][4];
    #pragma unroll
    for (int i = 0; i < 4; i++)
        #pragma unroll
        for (int j = 0; j < 4; j++)
            #pragma unroll
            for (int e = 0; e < 4; e++) acc[i][j][e] = 0.f;

#define SLOAD(fa, fb2, bufi) do {                                              \
    for (int t = tid; t < 1536; t += 256) {                                    \
        int sp = t >> 9; int rem = t & 511; int row = rem >> 2; int ck = rem & 3; \
        CP_ASYNC16(sb + ABUF(bufi, sp) + row * 80 + ck * 16,                   \
                   apz[sp] + (size_t)(s0 + row) * F + (fa) + ck * 8);          \
        CP_ASYNC16(sb + BBUF(bufi, sp) + row * 80 + ck * 16,                   \
                   bpz[sp] + (size_t)(n0 + row) * D + (fb2) + ck * 8);         \
    }                                                                          \
    asm volatile("cp.async.commit_group;");                                    \
} while (0)

    SLOAD(f0base, fob, 0);
    int buf = 0;
    for (int c = 0; c < 4; c++) {
        if (c < 3) {
            SLOAD(f0base + (c + 1) * 32, fob + (c + 1) * 32, buf ^ 1);
            asm volatile("cp.async.wait_group 1;");
        } else {
            asm volatile("cp.async.wait_group 0;");
        }
        __syncthreads();
        #pragma unroll
        for (int k16 = 0; k16 < 2; k16++) {
            uint32_t bfm[3][2][4];
            int brow = nw * 32 + ((lane >> 4) & 1) * 8 + (lane & 7);
            int bko = ((lane >> 3) & 1) * 16 + k16 * 32;
            #pragma unroll
            for (int sp = 0; sp < 3; sp++)
                #pragma unroll
                for (int q = 0; q < 2; q++)
                    LDSM4(bfm[sp][q], sb + BBUF(buf, sp) + (brow + q * 16) * 80 + bko);
            int amrow = mw * 64 + (lane & 15);
            int ako = (lane >> 4) * 16 + k16 * 32;
            #pragma unroll
            for (int i = 0; i < 3; i++) {
                uint32_t af[4][4];
                #pragma unroll
                for (int mt = 0; mt < 4; mt++)
                    LDSM4(af[mt], sb + ABUF(buf, i) + (amrow + mt * 16) * 80 + ako);
                #pragma unroll
                for (int j = 0; j < 3; j++) {
                    if (i + j > 2) continue;
                    #pragma unroll
                    for (int mt = 0; mt < 4; mt++) {
                        MMA_BF16(acc[mt][0], af[mt], bfm[j][0][0], bfm[j][0][1]);
                        MMA_BF16(acc[mt][1], af[mt], bfm[j][0][2], bfm[j][0][3]);
                        MMA_BF16(acc[mt][2], af[mt], bfm[j][1][0], bfm[j][1][1]);
                        MMA_BF16(acc[mt][3], af[mt], bfm[j][1][2], bfm[j][1][3]);
                    }
                }
            }
        }
        __syncthreads();
        buf ^= 1;
    }

    // store partials (fp32)
    int g = lane >> 2, tig = lane & 3;
    float* outp = g_spe_part[ks];
    #pragma unroll
    for (int mt = 0; mt < 4; mt++) {
        int r0 = s0 + mw * 64 + mt * 16 + g;
        #pragma unroll
        for (int nt = 0; nt < 4; nt++) {
            int dcol = n0 + nw * 32 + nt * 8 + tig * 2;
            outp[(size_t)r0 * D + dcol]           = acc[mt][nt][0];
            outp[(size_t)r0 * D + dcol + 1]       = acc[mt][nt][1];
            outp[(size_t)(r0 + 8) * D + dcol]     = acc[mt][nt][2];
            outp[(size_t)(r0 + 8) * D + dcol + 1] = acc[mt][nt][3];
        }
    }
}

// ---------------------------------------------------------------------------
// Kernel 3b: spe = sum of 8 partials + b1
__global__ void k_spe_combine(const float* __restrict__ b1) {
    int idx = blockIdx.x * 256 + threadIdx.x;
    float s = 0.f;
    #pragma unroll
    for (int p = 0; p < 8; p++) s += g_spe_part[p][idx];
    g_spe[idx] = s + b1[idx & (D - 1)];
}

// ---------------------------------------------------------------------------
// Kernel 5: main bf16 mma.sync GEMM (UNCHANGED from passing R8 version)
__global__ __launch_bounds__(256, 1) void k_gemm_mma(const float* __restrict__ w2v) {
    extern __shared__ __align__(16) char smem[];
    uint32_t sb = smem_u32(smem);
    int tid = threadIdx.x, wid = tid >> 5, lane = tid & 31;
    int bidx = blockIdx.x >> 4;                 // batch
    int st = (blockIdx.x >> 2) & 3;             // s-tile (128 rows)
    int nc = blockIdx.x & 3;                    // n-chunk (128 cols)
    int s0 = st * 128, n0 = nc * 128;
    int mw = wid & 1, nw = wid >> 1;            // 2 x 4 warp grid

    const __nv_bfloat16* aptr[3] = {g_as0, g_as1, g_as2};
    const __nv_bfloat16* bptr[3] = {g_w1t0, g_w1t1, g_w1t2};
    size_t arow0 = (size_t)(bidx * S + s0);
    size_t brow0 = (size_t)n0;

    float acc[4][4][4];
    #pragma unroll
    for (int i = 0; i < 4; i++)
        #pragma unroll
        for (int j = 0; j < 4; j++)
            #pragma unroll
            for (int e = 0; e < 4; e++) acc[i][j][e] = 0.f;

#define LOAD_CHUNK(f0, bufi) do {                                              \
    for (int t = tid; t < 1536; t += 256) {                                    \
        int sp = t >> 9; int rem = t & 511; int row = rem >> 2; int ck = rem & 3; \
        CP_ASYNC16(sb + ABUF(bufi, sp) + row * 80 + ck * 16,                   \
                   aptr[sp] + (arow0 + row) * D + (f0) + ck * 8);              \
        CP_ASYNC16(sb + BBUF(bufi, sp) + row * 80 + ck * 16,                   \
                   bptr[sp] + (brow0 + row) * D + (f0) + ck * 8);              \
    }                                                                          \
    asm volatile("cp.async.commit_group;");                                    \
} while (0)

    LOAD_CHUNK(0, 0);
    int buf = 0;

    for (int c = 0; c < 16; c++) {
        if (c < 15) {
            LOAD_CHUNK((c + 1) * 32, buf ^ 1);
            asm volatile("cp.async.wait_group 1;");
        } else {
            asm volatile("cp.async.wait_group 0;");
        }
        __syncthreads();

        #pragma unroll
        for (int k16 = 0; k16 < 2; k16++) {
            uint32_t bf[3][2][4];
            int brow = nw * 32 + ((lane >> 4) & 1) * 8 + (lane & 7);
            int bko = ((lane >> 3) & 1) * 16 + k16 * 32;
            #pragma unroll
            for (int sp = 0; sp < 3; sp++)
                #pragma unroll
                for (int q = 0; q < 2; q++)
                    LDSM4(bf[sp][q], sb + BBUF(buf, sp) + (brow + q * 16) * 80 + bko);

            int amrow = mw * 64 + (lane & 15);
            int ako = (lane >> 4) * 16 + k16 * 32;
            #pragma unroll
            for (int i = 0; i < 3; i++) {
                uint32_t af[4][4];
                #pragma unroll
                for (int mt = 0; mt < 4; mt++)
                    LDSM4(af[mt], sb + ABUF(buf, i) + (amrow + mt * 16) * 80 + ako);
                #pragma unroll
                for (int j = 0; j < 3; j++) {
                    if (i + j > 2) continue;
                    #pragma unroll
                    for (int mt = 0; mt < 4; mt++) {
                        MMA_BF16(acc[mt][0], af[mt], bf[j][0][0], bf[j][0][1]);
                        MMA_BF16(acc[mt][1], af[mt], bf[j][0][2], bf[j][0][3]);
                        MMA_BF16(acc[mt][2], af[mt], bf[j][1][0], bf[j][1][1]);
                        MMA_BF16(acc[mt][3], af[mt], bf[j][1][2], bf[j][1][3]);
                    }
                }
            }
        }
        __syncthreads();
        buf ^= 1;
    }

    // ---- epilogue: v += spe + gproj; relu; dot w2 -> partial scores ----
    float* scp = (float*)smem;
    int g = lane >> 2, tig = lane & 3;
    const float* gp = g_gproj + bidx * D;
    #pragma unroll
    for (int mt = 0; mt < 4; mt++) {
        int rl0 = mw * 64 + mt * 16 + g;
        int sg0 = s0 + rl0;
        float p0 = 0.f, p1 = 0.f;
        #pragma unroll
        for (int nt = 0; nt < 4; nt++) {
            #pragma unroll
            for (int e = 0; e < 2; e++) {
                int dcol = n0 + nw * 32 + nt * 8 + tig * 2 + e;
                float gpw = __ldg(&gp[dcol]);
                float wv  = __ldg(&w2v[dcol]);
                float v0 = acc[mt][nt][e]     + __ldg(&g_spe[(size_t)sg0 * D + dcol])       + gpw;
                float v1 = acc[mt][nt][2 + e] + __ldg(&g_spe[(size_t)(sg0 + 8) * D + dcol]) + gpw;
                if (v0 > 0.f) p0 += v0 * wv;
                if (v1 > 0.f) p1 += v1 * wv;
            }
        }
        p0 += __shfl_xor_sync(0xffffffffu, p0, 1);
        p0 += __shfl_xor_sync(0xffffffffu, p0, 2);
        p1 += __shfl_xor_sync(0xffffffffu, p1, 1);
        p1 += __shfl_xor_sync(0xffffffffu, p1, 2);
        if (tig == 0) {
            scp[rl0 * 4 + nw] = p0;
            scp[(rl0 + 8) * 4 + nw] = p1;
        }
    }
    __syncthreads();
    if (tid < 128)
        g_part[nc][bidx * S + s0 + tid] =
            (scp[tid * 4] + scp[tid * 4 + 1]) + (scp[tid * 4 + 2] + scp[tid * 4 + 3]);
}

// ---------------------------------------------------------------------------
// Kernel 6: sum partials, per-batch top-10, sort ascending, one-hot + gather.
__global__ void k_topk(float* __restrict__ out, const float* __restrict__ feat) {
    __shared__ float sv[S];
    __shared__ float rv[S];
    __shared__ int ri[S];
    __shared__ int sel[TOPK];
    int b = blockIdx.x;
    int t = threadIdx.x;
    int o = b * S + t;

    sv[t] = (g_part[0][o] + g_part[1][o]) + (g_part[2][o] + g_part[3][o]);

    for (int k = 0; k < TOPK; k++) {
        __syncthreads();
        rv[t] = sv[t];
        ri[t] = t;
        __syncthreads();
        for (int str = 256; str > 0; str >>= 1) {
            if (t < str) {
                float v2 = rv[t + str];
                int i2 = ri[t + str];
                if (v2 > rv[t] || (v2 == rv[t] && i2 < ri[t])) { rv[t] = v2; ri[t] = i2; }
            }
            __syncthreads();
        }
        if (t == 0) {
            sel[k] = ri[0];
            sv[ri[0]] = -INFINITY;
        }
    }
    __syncthreads();
    if (t == 0) {
        for (int i = 1; i < TOPK; i++) {
            int v = sel[i], j = i - 1;
            while (j >= 0 && sel[j] > v) { sel[j + 1] = sel[j]; j--; }
            sel[j + 1] = v;
        }
    }
    __syncthreads();

    float* oi = out + (size_t)b * TOPK * S;
    for (int i = t; i < TOPK * S; i += 512) {
        int k = i >> 9, s = i & (S - 1);
        oi[i] = (s == sel[k]) ? 1.0f : 0.0f;
    }
    float* os = out + (size_t)B * TOPK * S + (size_t)b * TOPK * D;
    const float* fb = feat + (size_t)b * S * D;
    for (int i = t; i < TOPK * D; i += 512) {
        int k = i >> 9, d = i & (D - 1);
        os[i] = fb[(size_t)sel[k] * D + d];
    }
}

// ---------------------------------------------------------------------------
extern "C" void kernel_launch(void* const* d_in, const int* in_sizes, int n_in,
                              void* d_out, int out_size) {
    (void)in_sizes; (void)n_in; (void)out_size;
    const float* x  = (const float*)d_in[0];
    const float* w1 = (const float*)d_in[1];
    const float* b1 = (const float*)d_in[2];
    const float* w2 = (const float*)d_in[3];
    // d_in[4] = b2: constant shift, does not affect top-k ordering -> unused.

    float* out = (float*)d_out;
    float* feat = out + (size_t)B * TOPK * S + (size_t)B * TOPK * D;

    cudaFuncSetAttribute(k_gemm_mma, cudaFuncAttributeMaxDynamicSharedMemorySize, SMEM_GEMM);
    cudaFuncSetAttribute(k_spe_mma, cudaFuncAttributeMaxDynamicSharedMemorySize, SMEM_GEMM);

    k_mean<<<(B * D) / 8, 256>>>(x);
    k_transpose<<<dim3(S / 32, D / 32, B), dim3(32, 8)>>>(x, feat);
    k_w1t<<<dim3(16, 32), dim3(32, 8)>>>(w1);
    k_pe<<<(S * F) / 256, 256>>>();
    k_gproj<<<512, 256>>>(w1);
    k_spe_mma<<<128, 256, SMEM_GEMM>>>();
    k_spe_combine<<<(S * D) / 256, 256>>>(b1);
    k_gemm_mma<<<B * 4 * 4, 256, SMEM_GEMM>>>(w2);
    k_topk<<<B, 512>>>(out, feat);
}

// round 13
// speedup vs baseline: 1.6029x; 1.3322x over previous
#include <cuda_runtime.h>
#include <cuda_bf16.h>
#include <math.h>
#include <stdint.h>

// Problem dims
#define B 128
#define D 512
#define S 512
#define F 1024     // 2*D
#define TOPK 10

// scratch (device globals: allocation-free)
__device__ float g_info[B * D];
__device__ float g_gproj[B * D];
__device__ float g_spe[S * D];
__device__ float g_spe_part[8][S * D];
__device__ float g_part[4][B * S];   // partial scores per 128-col chunk

// bf16 2-way splits of feat (A), W1a^T / W1b^T (B, [d][f] k-contig), pe
__device__ __nv_bfloat16 g_as0[B * S * D];
__device__ __nv_bfloat16 g_as1[B * S * D];
__device__ __nv_bfloat16 g_w1t0[D * D];
__device__ __nv_bfloat16 g_w1t1[D * D];
__device__ __nv_bfloat16 g_w1bt0[D * D];
__device__ __nv_bfloat16 g_w1bt1[D * D];
__device__ __nv_bfloat16 g_pe0[S * F];
__device__ __nv_bfloat16 g_pe1[S * F];

// ---------------- helpers ----------------
__device__ __forceinline__ uint32_t smem_u32(const void* p) {
    uint32_t a;
    asm("{ .reg .u64 t; cvta.to.shared.u64 t, %1; cvt.u32.u64 %0, t; }" : "=r"(a) : "l"(p));
    return a;
}
#define CP_ASYNC16(dst, src) \
    asm volatile("cp.async.cg.shared.global [%0], [%1], 16;" :: "r"(dst), "l"(src))

#define LDSM4(r, addr) \
    asm volatile("ldmatrix.sync.aligned.m8n8.x4.shared.b16 {%0,%1,%2,%3}, [%4];" \
        : "=r"((r)[0]), "=r"((r)[1]), "=r"((r)[2]), "=r"((r)[3]) : "r"(addr))

#define MMA_BF16(d, a, b0r, b1r) \
    asm volatile("mma.sync.aligned.m16n8k16.row.col.f32.bf16.bf16.f32 " \
        "{%0,%1,%2,%3}, {%4,%5,%6,%7}, {%8,%9}, {%0,%1,%2,%3};" \
        : "+f"((d)[0]), "+f"((d)[1]), "+f"((d)[2]), "+f"((d)[3]) \
        : "r"((a)[0]), "r"((a)[1]), "r"((a)[2]), "r"((a)[3]), "r"(b0r), "r"(b1r))

// split fp32 -> 2 bf16 terms (residual ~2^-18)
__device__ __forceinline__ void split2(float a, __nv_bfloat16& h0, __nv_bfloat16& h1) {
    h0 = __float2bfloat16(a);
    float r1 = a - __bfloat162float(h0);
    h1 = __float2bfloat16(r1);
}

// ---------------------------------------------------------------------------
// Kernel 1: row means of x
__global__ void k_mean(const float* __restrict__ x) {
    int row = blockIdx.x * 8 + (threadIdx.x >> 5);
    int lane = threadIdx.x & 31;
    const float4* p = (const float4*)(x + (size_t)row * S);
    float s = 0.f;
    #pragma unroll
    for (int i = lane; i < S / 4; i += 32) {
        float4 v = p[i];
        s += v.x + v.y + v.z + v.w;
    }
    #pragma unroll
    for (int o = 16; o; o >>= 1) s += __shfl_xor_sync(0xffffffffu, s, o);
    if (lane == 0) g_info[row] = s * (1.0f / (float)S);
}

// ---------------------------------------------------------------------------
// Kernel 2: feat[b,s,d] = x[b,d,s]; also emit 2-way bf16 splits of feat
__global__ void k_transpose(const float* __restrict__ x, float* __restrict__ feat) {
    __shared__ float tile[32][33];
    int b = blockIdx.z;
    int d0 = blockIdx.y * 32, s0 = blockIdx.x * 32;
    const float* xb = x + (size_t)b * D * S;
    float* fb = feat + (size_t)b * S * D;
    int tx = threadIdx.x;
    #pragma unroll
    for (int i = threadIdx.y; i < 32; i += 8)
        tile[i][tx] = xb[(size_t)(d0 + i) * S + s0 + tx];
    __syncthreads();
    #pragma unroll
    for (int i = threadIdx.y; i < 32; i += 8) {
        float a = tile[tx][i];
        size_t o = (size_t)b * S * D + (size_t)(s0 + i) * D + d0 + tx;
        fb[(size_t)(s0 + i) * D + d0 + tx] = a;
        __nv_bfloat16 h0, h1;
        split2(a, h0, h1);
        g_as0[o] = h0; g_as1[o] = h1;
    }
}

// ---------------------------------------------------------------------------
// Kernel 2b: transpose+split all of w1: [d][f] for f<512 -> w1t, f>=512 -> w1bt
__global__ void k_w1t(const float* __restrict__ w1) {
    __shared__ float tile[32][33];
    int f0 = blockIdx.y * 32, d0 = blockIdx.x * 32;
    int tx = threadIdx.x;
    #pragma unroll
    for (int i = threadIdx.y; i < 32; i += 8)
        tile[i][tx] = w1[(size_t)(f0 + i) * D + d0 + tx];
    __syncthreads();
    int hi = (f0 >= 512);
    __nv_bfloat16* o0 = hi ? g_w1bt0 : g_w1t0;
    __nv_bfloat16* o1 = hi ? g_w1bt1 : g_w1t1;
    int fb = f0 - hi * 512;
    #pragma unroll
    for (int i = threadIdx.y; i < 32; i += 8) {
        float a = tile[tx][i];  // = w1[f0+tx][d0+i]
        size_t o = (size_t)(d0 + i) * D + fb + tx;
        __nv_bfloat16 h0, h1;
        split2(a, h0, h1);
        o0[o] = h0; o1[o] = h1;
    }
}

// ---------------------------------------------------------------------------
// Kernel 2c: pe[s][f] sinusoid, 2-way bf16 split
__global__ void k_pe() {
    int idx = blockIdx.x * 256 + threadIdx.x;
    int s = idx >> 10, f = idx & 1023;
    int fe = f & ~1;
    float div = expf(-9.210340371976184f * (float)fe / (float)F);
    float ang = (float)s * div;
    float v = (f & 1) ? cosf(ang) : sinf(ang);
    __nv_bfloat16 h0, h1;
    split2(v, h0, h1);
    g_pe0[idx] = h0; g_pe1[idx] = h1;
}

// ---------------------------------------------------------------------------
// Kernel 4: g_proj[b,d] = sum_f info_g[b,f] * w1[D+f, d]
__global__ void k_gproj(const float* __restrict__ w1) {
    __shared__ float info_s[D];
    __shared__ float part[128];
    int tid = threadIdx.x;
    int b = blockIdx.x >> 2, dq = blockIdx.x & 3;
    info_s[tid] = g_info[b * D + tid];
    info_s[tid + 256] = g_info[b * D + tid + 256];
    __syncthreads();
    int fg = tid >> 7, dc = tid & 127;
    int d = dq * 128 + dc;
    const float* wb = w1 + (size_t)D * D + d;
    int fb = fg * 256;
    float a0 = 0.f, a1 = 0.f, a2 = 0.f, a3 = 0.f;
    #pragma unroll 4
    for (int f = 0; f < 256; f += 4) {
        a0 += info_s[fb + f]     * wb[(size_t)(fb + f) * D];
        a1 += info_s[fb + f + 1] * wb[(size_t)(fb + f + 1) * D];
        a2 += info_s[fb + f + 2] * wb[(size_t)(fb + f + 2) * D];
        a3 += info_s[fb + f + 3] * wb[(size_t)(fb + f + 3) * D];
    }
    float s = (a0 + a1) + (a2 + a3);
    if (fg == 1) part[dc] = s;
    __syncthreads();
    if (fg == 0) g_gproj[b * D + d] = s + part[dc];
}

// ---------------------------------------------------------------------------
// Shared GEMM tile layout (pitch 80B, Kc=32, double buffered, 2 splits)
#define PITCH 10240                      // 128 rows * 80 B per (split) tile
#define ABUF(buf, sp) (((buf) * 2 + (sp)) * PITCH)
#define BBUF(buf, sp) (40960 + ((buf) * 2 + (sp)) * PITCH)
#define SMEM_GEMM 81920

// ---------------------------------------------------------------------------
// Kernel 3: spe via HMMA: spe_part[ks] = pe[:, ks*128:(ks+1)*128] @ W1[ks-chunk]
// grid = 8(ks) x 4(st) x 4(nc) = 128 blocks; per block K=128 (4 chunks of 32).
__global__ __launch_bounds__(256, 1) void k_spe_mma() {
    extern __shared__ __align__(16) char smem[];
    uint32_t sb = smem_u32(smem);
    int tid = threadIdx.x, wid = tid >> 5, lane = tid & 31;
    int ks = blockIdx.x >> 4;
    int st = (blockIdx.x >> 2) & 3;
    int nc = blockIdx.x & 3;
    int s0 = st * 128, n0 = nc * 128;
    int mw = wid & 1, nw = wid >> 1;

    const __nv_bfloat16* apz[2] = {g_pe0, g_pe1};
    const __nv_bfloat16* bpz[2];
    int f0base = ks * 128;
    int fob;
    if (ks < 4) { bpz[0] = g_w1t0;  bpz[1] = g_w1t1;  fob = f0base; }
    else        { bpz[0] = g_w1bt0; bpz[1] = g_w1bt1; fob = f0base - 512; }

    float acc[4][4][4];
    #pragma unroll
    for (int i = 0; i < 4; i++)
        #pragma unroll
        for (int j = 0; j < 4; j++)
            #pragma unroll
            for (int e = 0; e < 4; e++) acc[i][j][e] = 0.f;

#define SLOAD(fa, fb2, bufi) do {                                              \
    for (int t = tid; t < 1024; t += 256) {                                    \
        int sp = t >> 9; int rem = t & 511; int row = rem >> 2; int ck = rem & 3; \
        CP_ASYNC16(sb + ABUF(bufi, sp) + row * 80 + ck * 16,                   \
                   apz[sp] + (size_t)(s0 + row) * F + (fa) + ck * 8);          \
        CP_ASYNC16(sb + BBUF(bufi, sp) + row * 80 + ck * 16,                   \
                   bpz[sp] + (size_t)(n0 + row) * D + (fb2) + ck * 8);         \
    }                                                                          \
    asm volatile("cp.async.commit_group;");                                    \
} while (0)

    SLOAD(f0base, fob, 0);
    int buf = 0;
    for (int c = 0; c < 4; c++) {
        if (c < 3) {
            SLOAD(f0base + (c + 1) * 32, fob + (c + 1) * 32, buf ^ 1);
            asm volatile("cp.async.wait_group 1;");
        } else {
            asm volatile("cp.async.wait_group 0;");
        }
        __syncthreads();
        #pragma unroll
        for (int k16 = 0; k16 < 2; k16++) {
            uint32_t bfm[2][2][4];
            int brow = nw * 32 + ((lane >> 4) & 1) * 8 + (lane & 7);
            int bko = ((lane >> 3) & 1) * 16 + k16 * 32;
            #pragma unroll
            for (int sp = 0; sp < 2; sp++)
                #pragma unroll
                for (int q = 0; q < 2; q++)
                    LDSM4(bfm[sp][q], sb + BBUF(buf, sp) + (brow + q * 16) * 80 + bko);
            int amrow = mw * 64 + (lane & 15);
            int ako = (lane >> 4) * 16 + k16 * 32;
            #pragma unroll
            for (int i = 0; i < 2; i++) {
                uint32_t af[4][4];
                #pragma unroll
                for (int mt = 0; mt < 4; mt++)
                    LDSM4(af[mt], sb + ABUF(buf, i) + (amrow + mt * 16) * 80 + ako);
                #pragma unroll
                for (int j = 0; j < 2; j++) {
                    #pragma unroll
                    for (int mt = 0; mt < 4; mt++) {
                        MMA_BF16(acc[mt][0], af[mt], bfm[j][0][0], bfm[j][0][1]);
                        MMA_BF16(acc[mt][1], af[mt], bfm[j][0][2], bfm[j][0][3]);
                        MMA_BF16(acc[mt][2], af[mt], bfm[j][1][0], bfm[j][1][1]);
                        MMA_BF16(acc[mt][3], af[mt], bfm[j][1][2], bfm[j][1][3]);
                    }
                }
            }
        }
        __syncthreads();
        buf ^= 1;
    }

    // store partials (fp32)
    int g = lane >> 2, tig = lane & 3;
    float* outp = g_spe_part[ks];
    #pragma unroll
    for (int mt = 0; mt < 4; mt++) {
        int r0 = s0 + mw * 64 + mt * 16 + g;
        #pragma unroll
        for (int nt = 0; nt < 4; nt++) {
            int dcol = n0 + nw * 32 + nt * 8 + tig * 2;
            outp[(size_t)r0 * D + dcol]           = acc[mt][nt][0];
            outp[(size_t)r0 * D + dcol + 1]       = acc[mt][nt][1];
            outp[(size_t)(r0 + 8) * D + dcol]     = acc[mt][nt][2];
            outp[(size_t)(r0 + 8) * D + dcol + 1] = acc[mt][nt][3];
        }
    }
}

// ---------------------------------------------------------------------------
// Kernel 3b: spe = sum of 8 partials + b1
__global__ void k_spe_combine(const float* __restrict__ b1) {
    int idx = blockIdx.x * 256 + threadIdx.x;
    float s = 0.f;
    #pragma unroll
    for (int p = 0; p < 8; p++) s += g_spe_part[p][idx];
    g_spe[idx] = s + b1[idx & (D - 1)];
}

// ---------------------------------------------------------------------------
// Kernel 5: main bf16 mma.sync GEMM (2-split, 4 products)
__global__ __launch_bounds__(256, 1) void k_gemm_mma(const float* __restrict__ w2v) {
    extern __shared__ __align__(16) char smem[];
    uint32_t sb = smem_u32(smem);
    int tid = threadIdx.x, wid = tid >> 5, lane = tid & 31;
    int bidx = blockIdx.x >> 4;                 // batch
    int st = (blockIdx.x >> 2) & 3;             // s-tile (128 rows)
    int nc = blockIdx.x & 3;                    // n-chunk (128 cols)
    int s0 = st * 128, n0 = nc * 128;
    int mw = wid & 1, nw = wid >> 1;            // 2 x 4 warp grid

    const __nv_bfloat16* aptr[2] = {g_as0, g_as1};
    const __nv_bfloat16* bptr[2] = {g_w1t0, g_w1t1};
    size_t arow0 = (size_t)(bidx * S + s0);
    size_t brow0 = (size_t)n0;

    float acc[4][4][4];
    #pragma unroll
    for (int i = 0; i < 4; i++)
        #pragma unroll
        for (int j = 0; j < 4; j++)
            #pragma unroll
            for (int e = 0; e < 4; e++) acc[i][j][e] = 0.f;

#define LOAD_CHUNK(f0, bufi) do {                                              \
    for (int t = tid; t < 1024; t += 256) {                                    \
        int sp = t >> 9; int rem = t & 511; int row = rem >> 2; int ck = rem & 3; \
        CP_ASYNC16(sb + ABUF(bufi, sp) + row * 80 + ck * 16,                   \
                   aptr[sp] + (arow0 + row) * D + (f0) + ck * 8);              \
        CP_ASYNC16(sb + BBUF(bufi, sp) + row * 80 + ck * 16,                   \
                   bptr[sp] + (brow0 + row) * D + (f0) + ck * 8);              \
    }                                                                          \
    asm volatile("cp.async.commit_group;");                                    \
} while (0)

    LOAD_CHUNK(0, 0);
    int buf = 0;

    for (int c = 0; c < 16; c++) {
        if (c < 15) {
            LOAD_CHUNK((c + 1) * 32, buf ^ 1);
            asm volatile("cp.async.wait_group 1;");
        } else {
            asm volatile("cp.async.wait_group 0;");
        }
        __syncthreads();

        #pragma unroll
        for (int k16 = 0; k16 < 2; k16++) {
            uint32_t bf[2][2][4];
            int brow = nw * 32 + ((lane >> 4) & 1) * 8 + (lane & 7);
            int bko = ((lane >> 3) & 1) * 16 + k16 * 32;
            #pragma unroll
            for (int sp = 0; sp < 2; sp++)
                #pragma unroll
                for (int q = 0; q < 2; q++)
                    LDSM4(bf[sp][q], sb + BBUF(buf, sp) + (brow + q * 16) * 80 + bko);

            int amrow = mw * 64 + (lane & 15);
            int ako = (lane >> 4) * 16 + k16 * 32;
            #pragma unroll
            for (int i = 0; i < 2; i++) {
                uint32_t af[4][4];
                #pragma unroll
                for (int mt = 0; mt < 4; mt++)
                    LDSM4(af[mt], sb + ABUF(buf, i) + (amrow + mt * 16) * 80 + ako);
                #pragma unroll
                for (int j = 0; j < 2; j++) {
                    #pragma unroll
                    for (int mt = 0; mt < 4; mt++) {
                        MMA_BF16(acc[mt][0], af[mt], bf[j][0][0], bf[j][0][1]);
                        MMA_BF16(acc[mt][1], af[mt], bf[j][0][2], bf[j][0][3]);
                        MMA_BF16(acc[mt][2], af[mt], bf[j][1][0], bf[j][1][1]);
                        MMA_BF16(acc[mt][3], af[mt], bf[j][1][2], bf[j][1][3]);
                    }
                }
            }
        }
        __syncthreads();
        buf ^= 1;
    }

    // ---- epilogue: v += spe + gproj; relu; dot w2 -> partial scores ----
    float* scp = (float*)smem;
    int g = lane >> 2, tig = lane & 3;
    const float* gp = g_gproj + bidx * D;
    #pragma unroll
    for (int mt = 0; mt < 4; mt++) {
        int rl0 = mw * 64 + mt * 16 + g;
        int sg0 = s0 + rl0;
        float p0 = 0.f, p1 = 0.f;
        #pragma unroll
        for (int nt = 0; nt < 4; nt++) {
            #pragma unroll
            for (int e = 0; e < 2; e++) {
                int dcol = n0 + nw * 32 + nt * 8 + tig * 2 + e;
                float gpw = __ldg(&gp[dcol]);
                float wv  = __ldg(&w2v[dcol]);
                float v0 = acc[mt][nt][e]     + __ldg(&g_spe[(size_t)sg0 * D + dcol])       + gpw;
                float v1 = acc[mt][nt][2 + e] + __ldg(&g_spe[(size_t)(sg0 + 8) * D + dcol]) + gpw;
                if (v0 > 0.f) p0 += v0 * wv;
                if (v1 > 0.f) p1 += v1 * wv;
            }
        }
        p0 += __shfl_xor_sync(0xffffffffu, p0, 1);
        p0 += __shfl_xor_sync(0xffffffffu, p0, 2);
        p1 += __shfl_xor_sync(0xffffffffu, p1, 1);
        p1 += __shfl_xor_sync(0xffffffffu, p1, 2);
        if (tig == 0) {
            scp[rl0 * 4 + nw] = p0;
            scp[(rl0 + 8) * 4 + nw] = p1;
        }
    }
    __syncthreads();
    if (tid < 128)
        g_part[nc][bidx * S + s0 + tid] =
            (scp[tid * 4] + scp[tid * 4 + 1]) + (scp[tid * 4 + 2] + scp[tid * 4 + 3]);
}

// ---------------------------------------------------------------------------
// Kernel 6: sum partials, per-batch top-10, sort ascending, one-hot + gather.
__global__ void k_topk(float* __restrict__ out, const float* __restrict__ feat) {
    __shared__ float sv[S];
    __shared__ float rv[S];
    __shared__ int ri[S];
    __shared__ int sel[TOPK];
    int b = blockIdx.x;
    int t = threadIdx.x;
    int o = b * S + t;

    sv[t] = (g_part[0][o] + g_part[1][o]) + (g_part[2][o] + g_part[3][o]);

    for (int k = 0; k < TOPK; k++) {
        __syncthreads();
        rv[t] = sv[t];
        ri[t] = t;
        __syncthreads();
        for (int str = 256; str > 0; str >>= 1) {
            if (t < str) {
                float v2 = rv[t + str];
                int i2 = ri[t + str];
                if (v2 > rv[t] || (v2 == rv[t] && i2 < ri[t])) { rv[t] = v2; ri[t] = i2; }
            }
            __syncthreads();
        }
        if (t == 0) {
            sel[k] = ri[0];
            sv[ri[0]] = -INFINITY;
        }
    }
    __syncthreads();
    if (t == 0) {
        for (int i = 1; i < TOPK; i++) {
            int v = sel[i], j = i - 1;
            while (j >= 0 && sel[j] > v) { sel[j + 1] = sel[j]; j--; }
            sel[j + 1] = v;
        }
    }
    __syncthreads();

    float* oi = out + (size_t)b * TOPK * S;
    for (int i = t; i < TOPK * S; i += 512) {
        int k = i >> 9, s = i & (S - 1);
        oi[i] = (s == sel[k]) ? 1.0f : 0.0f;
    }
    float* os = out + (size_t)B * TOPK * S + (size_t)b * TOPK * D;
    const float* fb = feat + (size_t)b * S * D;
    for (int i = t; i < TOPK * D; i += 512) {
        int k = i >> 9, d = i & (D - 1);
        os[i] = fb[(size_t)sel[k] * D + d];
    }
}

// ---------------------------------------------------------------------------
extern "C" void kernel_launch(void* const* d_in, const int* in_sizes, int n_in,
                              void* d_out, int out_size) {
    (void)in_sizes; (void)n_in; (void)out_size;
    const float* x  = (const float*)d_in[0];
    const float* w1 = (const float*)d_in[1];
    const float* b1 = (const float*)d_in[2];
    const float* w2 = (const float*)d_in[3];
    // d_in[4] = b2: constant shift, does not affect top-k ordering -> unused.

    float* out = (float*)d_out;
    float* feat = out + (size_t)B * TOPK * S + (size_t)B * TOPK * D;

    cudaFuncSetAttribute(k_gemm_mma, cudaFuncAttributeMaxDynamicSharedMemorySize, SMEM_GEMM);
    cudaFuncSetAttribute(k_spe_mma, cudaFuncAttributeMaxDynamicSharedMemorySize, SMEM_GEMM);

    k_mean<<<(B * D) / 8, 256>>>(x);
    k_transpose<<<dim3(S / 32, D / 32, B), dim3(32, 8)>>>(x, feat);
    k_w1t<<<dim3(16, 32), dim3(32, 8)>>>(w1);
    k_pe<<<(S * F) / 256, 256>>>();
    k_gproj<<<512, 256>>>(w1);
    k_spe_mma<<<128, 256, SMEM_GEMM>>>();
    k_spe_combine<<<(S * D) / 256, 256>>>(b1);
    k_gemm_mma<<<B * 4 * 4, 256, SMEM_GEMM>>>(w2);
    k_topk<<<B, 512>>>(out, feat);
}

// round 14
// speedup vs baseline: 1.9012x; 1.1861x over previous
#include <cuda_runtime.h>
#include <cuda_bf16.h>
#include <math.h>
#include <stdint.h>

// Problem dims
#define B 128
#define D 512
#define S 512
#define F 1024     // 2*D
#define TOPK 10

// scratch (device globals: allocation-free)
__device__ float g_info[B * D];
__device__ float g_gproj[B * D];
__device__ float g_spe[S * D];
__device__ float g_spe_part[8][S * D];
__device__ float g_part[4][B * S];   // partial scores per 128-col chunk

// bf16 2-way splits of feat (A), W1a^T / W1b^T (B, [d][f] k-contig), pe
__device__ __nv_bfloat16 g_as0[B * S * D];
__device__ __nv_bfloat16 g_as1[B * S * D];
__device__ __nv_bfloat16 g_w1t0[D * D];
__device__ __nv_bfloat16 g_w1t1[D * D];
__device__ __nv_bfloat16 g_w1bt0[D * D];
__device__ __nv_bfloat16 g_w1bt1[D * D];
__device__ __nv_bfloat16 g_pe0[S * F];
__device__ __nv_bfloat16 g_pe1[S * F];

// ---------------- helpers ----------------
__device__ __forceinline__ uint32_t smem_u32(const void* p) {
    uint32_t a;
    asm("{ .reg .u64 t; cvta.to.shared.u64 t, %1; cvt.u32.u64 %0, t; }" : "=r"(a) : "l"(p));
    return a;
}
#define CP_ASYNC16(dst, src) \
    asm volatile("cp.async.cg.shared.global [%0], [%1], 16;" :: "r"(dst), "l"(src))

#define LDSM4(r, addr) \
    asm volatile("ldmatrix.sync.aligned.m8n8.x4.shared.b16 {%0,%1,%2,%3}, [%4];" \
        : "=r"((r)[0]), "=r"((r)[1]), "=r"((r)[2]), "=r"((r)[3]) : "r"(addr))

#define MMA_BF16(d, a, b0r, b1r) \
    asm volatile("mma.sync.aligned.m16n8k16.row.col.f32.bf16.bf16.f32 " \
        "{%0,%1,%2,%3}, {%4,%5,%6,%7}, {%8,%9}, {%0,%1,%2,%3};" \
        : "+f"((d)[0]), "+f"((d)[1]), "+f"((d)[2]), "+f"((d)[3]) \
        : "r"((a)[0]), "r"((a)[1]), "r"((a)[2]), "r"((a)[3]), "r"(b0r), "r"(b1r))

// split fp32 -> 2 bf16 terms (residual ~2^-18)
__device__ __forceinline__ void split2(float a, __nv_bfloat16& h0, __nv_bfloat16& h1) {
    h0 = __float2bfloat16(a);
    float r1 = a - __bfloat162float(h0);
    h1 = __float2bfloat16(r1);
}

// ---------------------------------------------------------------------------
// Kernel 1: row means of x
__global__ void k_mean(const float* __restrict__ x) {
    int row = blockIdx.x * 8 + (threadIdx.x >> 5);
    int lane = threadIdx.x & 31;
    const float4* p = (const float4*)(x + (size_t)row * S);
    float s = 0.f;
    #pragma unroll
    for (int i = lane; i < S / 4; i += 32) {
        float4 v = p[i];
        s += v.x + v.y + v.z + v.w;
    }
    #pragma unroll
    for (int o = 16; o; o >>= 1) s += __shfl_xor_sync(0xffffffffu, s, o);
    if (lane == 0) g_info[row] = s * (1.0f / (float)S);
}

// ---------------------------------------------------------------------------
// Kernel 2: feat[b,s,d] = x[b,d,s]; also emit 2-way bf16 splits of feat
__global__ void k_transpose(const float* __restrict__ x, float* __restrict__ feat) {
    __shared__ float tile[32][33];
    int b = blockIdx.z;
    int d0 = blockIdx.y * 32, s0 = blockIdx.x * 32;
    const float* xb = x + (size_t)b * D * S;
    float* fb = feat + (size_t)b * S * D;
    int tx = threadIdx.x;
    #pragma unroll
    for (int i = threadIdx.y; i < 32; i += 8)
        tile[i][tx] = xb[(size_t)(d0 + i) * S + s0 + tx];
    __syncthreads();
    #pragma unroll
    for (int i = threadIdx.y; i < 32; i += 8) {
        float a = tile[tx][i];
        size_t o = (size_t)b * S * D + (size_t)(s0 + i) * D + d0 + tx;
        fb[(size_t)(s0 + i) * D + d0 + tx] = a;
        __nv_bfloat16 h0, h1;
        split2(a, h0, h1);
        g_as0[o] = h0; g_as1[o] = h1;
    }
}

// ---------------------------------------------------------------------------
// Kernel 2b: transpose+split all of w1: [d][f] for f<512 -> w1t, f>=512 -> w1bt
__global__ void k_w1t(const float* __restrict__ w1) {
    __shared__ float tile[32][33];
    int f0 = blockIdx.y * 32, d0 = blockIdx.x * 32;
    int tx = threadIdx.x;
    #pragma unroll
    for (int i = threadIdx.y; i < 32; i += 8)
        tile[i][tx] = w1[(size_t)(f0 + i) * D + d0 + tx];
    __syncthreads();
    int hi = (f0 >= 512);
    __nv_bfloat16* o0 = hi ? g_w1bt0 : g_w1t0;
    __nv_bfloat16* o1 = hi ? g_w1bt1 : g_w1t1;
    int fb = f0 - hi * 512;
    #pragma unroll
    for (int i = threadIdx.y; i < 32; i += 8) {
        float a = tile[tx][i];  // = w1[f0+tx][d0+i]
        size_t o = (size_t)(d0 + i) * D + fb + tx;
        __nv_bfloat16 h0, h1;
        split2(a, h0, h1);
        o0[o] = h0; o1[o] = h1;
    }
}

// ---------------------------------------------------------------------------
// Kernel 2c: pe[s][f] sinusoid, 2-way bf16 split
__global__ void k_pe() {
    int idx = blockIdx.x * 256 + threadIdx.x;
    int s = idx >> 10, f = idx & 1023;
    int fe = f & ~1;
    float div = expf(-9.210340371976184f * (float)fe / (float)F);
    float ang = (float)s * div;
    float v = (f & 1) ? cosf(ang) : sinf(ang);
    __nv_bfloat16 h0, h1;
    split2(v, h0, h1);
    g_pe0[idx] = h0; g_pe1[idx] = h1;
}

// ---------------------------------------------------------------------------
// Kernel 4: g_proj[b,d] = sum_f info_g[b,f] * w1[D+f, d]
__global__ void k_gproj(const float* __restrict__ w1) {
    __shared__ float info_s[D];
    __shared__ float part[128];
    int tid = threadIdx.x;
    int b = blockIdx.x >> 2, dq = blockIdx.x & 3;
    info_s[tid] = g_info[b * D + tid];
    info_s[tid + 256] = g_info[b * D + tid + 256];
    __syncthreads();
    int fg = tid >> 7, dc = tid & 127;
    int d = dq * 128 + dc;
    const float* wb = w1 + (size_t)D * D + d;
    int fb = fg * 256;
    float a0 = 0.f, a1 = 0.f, a2 = 0.f, a3 = 0.f;
    #pragma unroll 4
    for (int f = 0; f < 256; f += 4) {
        a0 += info_s[fb + f]     * wb[(size_t)(fb + f) * D];
        a1 += info_s[fb + f + 1] * wb[(size_t)(fb + f + 1) * D];
        a2 += info_s[fb + f + 2] * wb[(size_t)(fb + f + 2) * D];
        a3 += info_s[fb + f + 3] * wb[(size_t)(fb + f + 3) * D];
    }
    float s = (a0 + a1) + (a2 + a3);
    if (fg == 1) part[dc] = s;
    __syncthreads();
    if (fg == 0) g_gproj[b * D + d] = s + part[dc];
}

// ---------------------------------------------------------------------------
// Shared GEMM tile layout (pitch 80B, Kc=32, double buffered, 2 splits)
#define PITCH 10240                      // 128 rows * 80 B per (split) tile
#define ABUF(buf, sp) (((buf) * 2 + (sp)) * PITCH)
#define BBUF(buf, sp) (40960 + ((buf) * 2 + (sp)) * PITCH)
#define SMEM_GEMM 81920

// ---------------------------------------------------------------------------
// Kernel 3: spe via HMMA: spe_part[ks] = pe[:, ks*128:(ks+1)*128] @ W1[ks-chunk]
// grid = 8(ks) x 4(st) x 4(nc) = 128 blocks; per block K=128 (4 chunks of 32).
__global__ __launch_bounds__(256, 1) void k_spe_mma() {
    extern __shared__ __align__(16) char smem[];
    uint32_t sb = smem_u32(smem);
    int tid = threadIdx.x, wid = tid >> 5, lane = tid & 31;
    int ks = blockIdx.x >> 4;
    int st = (blockIdx.x >> 2) & 3;
    int nc = blockIdx.x & 3;
    int s0 = st * 128, n0 = nc * 128;
    int mw = wid & 1, nw = wid >> 1;

    const __nv_bfloat16* apz[2] = {g_pe0, g_pe1};
    const __nv_bfloat16* bpz[2];
    int f0base = ks * 128;
    int fob;
    if (ks < 4) { bpz[0] = g_w1t0;  bpz[1] = g_w1t1;  fob = f0base; }
    else        { bpz[0] = g_w1bt0; bpz[1] = g_w1bt1; fob = f0base - 512; }

    float acc[4][4][4];
    #pragma unroll
    for (int i = 0; i < 4; i++)
        #pragma unroll
        for (int j = 0; j < 4; j++)
            #pragma unroll
            for (int e = 0; e < 4; e++) acc[i][j][e] = 0.f;

#define SLOAD(fa, fb2, bufi) do {                                              \
    for (int t = tid; t < 1024; t += 256) {                                    \
        int sp = t >> 9; int rem = t & 511; int row = rem >> 2; int ck = rem & 3; \
        CP_ASYNC16(sb + ABUF(bufi, sp) + row * 80 + ck * 16,                   \
                   apz[sp] + (size_t)(s0 + row) * F + (fa) + ck * 8);          \
        CP_ASYNC16(sb + BBUF(bufi, sp) + row * 80 + ck * 16,                   \
                   bpz[sp] + (size_t)(n0 + row) * D + (fb2) + ck * 8);         \
    }                                                                          \
    asm volatile("cp.async.commit_group;");                                    \
} while (0)

    SLOAD(f0base, fob, 0);
    int buf = 0;
    for (int c = 0; c < 4; c++) {
        if (c < 3) {
            SLOAD(f0base + (c + 1) * 32, fob + (c + 1) * 32, buf ^ 1);
            asm volatile("cp.async.wait_group 1;");
        } else {
            asm volatile("cp.async.wait_group 0;");
        }
        __syncthreads();
        #pragma unroll
        for (int k16 = 0; k16 < 2; k16++) {
            uint32_t bfm[2][2][4];
            int brow = nw * 32 + ((lane >> 4) & 1) * 8 + (lane & 7);
            int bko = ((lane >> 3) & 1) * 16 + k16 * 32;
            #pragma unroll
            for (int sp = 0; sp < 2; sp++)
                #pragma unroll
                for (int q = 0; q < 2; q++)
                    LDSM4(bfm[sp][q], sb + BBUF(buf, sp) + (brow + q * 16) * 80 + bko);
            int amrow = mw * 64 + (lane & 15);
            int ako = (lane >> 4) * 16 + k16 * 32;
            #pragma unroll
            for (int i = 0; i < 2; i++) {
                uint32_t af[4][4];
                #pragma unroll
                for (int mt = 0; mt < 4; mt++)
                    LDSM4(af[mt], sb + ABUF(buf, i) + (amrow + mt * 16) * 80 + ako);
                #pragma unroll
                for (int j = 0; j < 2; j++) {
                    #pragma unroll
                    for (int mt = 0; mt < 4; mt++) {
                        MMA_BF16(acc[mt][0], af[mt], bfm[j][0][0], bfm[j][0][1]);
                        MMA_BF16(acc[mt][1], af[mt], bfm[j][0][2], bfm[j][0][3]);
                        MMA_BF16(acc[mt][2], af[mt], bfm[j][1][0], bfm[j][1][1]);
                        MMA_BF16(acc[mt][3], af[mt], bfm[j][1][2], bfm[j][1][3]);
                    }
                }
            }
        }
        __syncthreads();
        buf ^= 1;
    }

    // store partials (fp32)
    int g = lane >> 2, tig = lane & 3;
    float* outp = g_spe_part[ks];
    #pragma unroll
    for (int mt = 0; mt < 4; mt++) {
        int r0 = s0 + mw * 64 + mt * 16 + g;
        #pragma unroll
        for (int nt = 0; nt < 4; nt++) {
            int dcol = n0 + nw * 32 + nt * 8 + tig * 2;
            outp[(size_t)r0 * D + dcol]           = acc[mt][nt][0];
            outp[(size_t)r0 * D + dcol + 1]       = acc[mt][nt][1];
            outp[(size_t)(r0 + 8) * D + dcol]     = acc[mt][nt][2];
            outp[(size_t)(r0 + 8) * D + dcol + 1] = acc[mt][nt][3];
        }
    }
}

// ---------------------------------------------------------------------------
// Kernel 3b: spe = sum of 8 partials + b1
__global__ void k_spe_combine(const float* __restrict__ b1) {
    int idx = blockIdx.x * 256 + threadIdx.x;
    float s = 0.f;
    #pragma unroll
    for (int p = 0; p < 8; p++) s += g_spe_part[p][idx];
    g_spe[idx] = s + b1[idx & (D - 1)];
}

// ---------------------------------------------------------------------------
// Kernel 5: main bf16 mma.sync GEMM (2-split, 4 products), 2 CTAs/SM
__global__ __launch_bounds__(256, 2) void k_gemm_mma(const float* __restrict__ w2v) {
    extern __shared__ __align__(16) char smem[];
    uint32_t sb = smem_u32(smem);
    int tid = threadIdx.x, wid = tid >> 5, lane = tid & 31;
    int bidx = blockIdx.x >> 4;                 // batch
    int st = (blockIdx.x >> 2) & 3;             // s-tile (128 rows)
    int nc = blockIdx.x & 3;                    // n-chunk (128 cols)
    int s0 = st * 128, n0 = nc * 128;
    int mw = wid & 1, nw = wid >> 1;            // 2 x 4 warp grid

    const __nv_bfloat16* aptr[2] = {g_as0, g_as1};
    const __nv_bfloat16* bptr[2] = {g_w1t0, g_w1t1};
    size_t arow0 = (size_t)(bidx * S + s0);
    size_t brow0 = (size_t)n0;

    float acc[4][4][4];
    #pragma unroll
    for (int i = 0; i < 4; i++)
        #pragma unroll
        for (int j = 0; j < 4; j++)
            #pragma unroll
            for (int e = 0; e < 4; e++) acc[i][j][e] = 0.f;

#define LOAD_CHUNK(f0, bufi) do {                                              \
    for (int t = tid; t < 1024; t += 256) {                                    \
        int sp = t >> 9; int rem = t & 511; int row = rem >> 2; int ck = rem & 3; \
        CP_ASYNC16(sb + ABUF(bufi, sp) + row * 80 + ck * 16,                   \
                   aptr[sp] + (arow0 + row) * D + (f0) + ck * 8);              \
        CP_ASYNC16(sb + BBUF(bufi, sp) + row * 80 + ck * 16,                   \
                   bptr[sp] + (brow0 + row) * D + (f0) + ck * 8);              \
    }                                                                          \
    asm volatile("cp.async.commit_group;");                                    \
} while (0)

    LOAD_CHUNK(0, 0);
    int buf = 0;

    for (int c = 0; c < 16; c++) {
        if (c < 15) {
            LOAD_CHUNK((c + 1) * 32, buf ^ 1);
            asm volatile("cp.async.wait_group 1;");
        } else {
            asm volatile("cp.async.wait_group 0;");
        }
        __syncthreads();

        #pragma unroll
        for (int k16 = 0; k16 < 2; k16++) {
            uint32_t bf[2][2][4];
            int brow = nw * 32 + ((lane >> 4) & 1) * 8 + (lane & 7);
            int bko = ((lane >> 3) & 1) * 16 + k16 * 32;
            #pragma unroll
            for (int sp = 0; sp < 2; sp++)
                #pragma unroll
                for (int q = 0; q < 2; q++)
                    LDSM4(bf[sp][q], sb + BBUF(buf, sp) + (brow + q * 16) * 80 + bko);

            int amrow = mw * 64 + (lane & 15);
            int ako = (lane >> 4) * 16 + k16 * 32;
            #pragma unroll
            for (int i = 0; i < 2; i++) {
                uint32_t af[4][4];
                #pragma unroll
                for (int mt = 0; mt < 4; mt++)
                    LDSM4(af[mt], sb + ABUF(buf, i) + (amrow + mt * 16) * 80 + ako);
                #pragma unroll
                for (int j = 0; j < 2; j++) {
                    #pragma unroll
                    for (int mt = 0; mt < 4; mt++) {
                        MMA_BF16(acc[mt][0], af[mt], bf[j][0][0], bf[j][0][1]);
                        MMA_BF16(acc[mt][1], af[mt], bf[j][0][2], bf[j][0][3]);
                        MMA_BF16(acc[mt][2], af[mt], bf[j][1][0], bf[j][1][1]);
                        MMA_BF16(acc[mt][3], af[mt], bf[j][1][2], bf[j][1][3]);
                    }
                }
            }
        }
        __syncthreads();
        buf ^= 1;
    }

    // ---- epilogue: v += spe + gproj; relu; dot w2 -> partial scores ----
    float* scp = (float*)smem;
    int g = lane >> 2, tig = lane & 3;
    const float* gp = g_gproj + bidx * D;
    #pragma unroll
    for (int mt = 0; mt < 4; mt++) {
        int rl0 = mw * 64 + mt * 16 + g;
        int sg0 = s0 + rl0;
        float p0 = 0.f, p1 = 0.f;
        #pragma unroll
        for (int nt = 0; nt < 4; nt++) {
            #pragma unroll
            for (int e = 0; e < 2; e++) {
                int dcol = n0 + nw * 32 + nt * 8 + tig * 2 + e;
                float gpw = __ldg(&gp[dcol]);
                float wv  = __ldg(&w2v[dcol]);
                float v0 = acc[mt][nt][e]     + __ldg(&g_spe[(size_t)sg0 * D + dcol])       + gpw;
                float v1 = acc[mt][nt][2 + e] + __ldg(&g_spe[(size_t)(sg0 + 8) * D + dcol]) + gpw;
                if (v0 > 0.f) p0 += v0 * wv;
                if (v1 > 0.f) p1 += v1 * wv;
            }
        }
        p0 += __shfl_xor_sync(0xffffffffu, p0, 1);
        p0 += __shfl_xor_sync(0xffffffffu, p0, 2);
        p1 += __shfl_xor_sync(0xffffffffu, p1, 1);
        p1 += __shfl_xor_sync(0xffffffffu, p1, 2);
        if (tig == 0) {
            scp[rl0 * 4 + nw] = p0;
            scp[(rl0 + 8) * 4 + nw] = p1;
        }
    }
    __syncthreads();
    if (tid < 128)
        g_part[nc][bidx * S + s0 + tid] =
            (scp[tid * 4] + scp[tid * 4 + 1]) + (scp[tid * 4 + 2] + scp[tid * 4 + 3]);
}

// ---------------------------------------------------------------------------
// Kernel 6: sum partials, per-batch top-10, sort ascending, one-hot + gather.
__global__ void k_topk(float* __restrict__ out, const float* __restrict__ feat) {
    __shared__ float sv[S];
    __shared__ float rv[S];
    __shared__ int ri[S];
    __shared__ int sel[TOPK];
    int b = blockIdx.x;
    int t = threadIdx.x;
    int o = b * S + t;

    sv[t] = (g_part[0][o] + g_part[1][o]) + (g_part[2][o] + g_part[3][o]);

    for (int k = 0; k < TOPK; k++) {
        __syncthreads();
        rv[t] = sv[t];
        ri[t] = t;
        __syncthreads();
        for (int str = 256; str > 0; str >>= 1) {
            if (t < str) {
                float v2 = rv[t + str];
                int i2 = ri[t + str];
                if (v2 > rv[t] || (v2 == rv[t] && i2 < ri[t])) { rv[t] = v2; ri[t] = i2; }
            }
            __syncthreads();
        }
        if (t == 0) {
            sel[k] = ri[0];
            sv[ri[0]] = -INFINITY;
        }
    }
    __syncthreads();
    if (t == 0) {
        for (int i = 1; i < TOPK; i++) {
            int v = sel[i], j = i - 1;
            while (j >= 0 && sel[j] > v) { sel[j + 1] = sel[j]; j--; }
            sel[j + 1] = v;
        }
    }
    __syncthreads();

    float* oi = out + (size_t)b * TOPK * S;
    for (int i = t; i < TOPK * S; i += 512) {
        int k = i >> 9, s = i & (S - 1);
        oi[i] = (s == sel[k]) ? 1.0f : 0.0f;
    }
    float* os = out + (size_t)B * TOPK * S + (size_t)b * TOPK * D;
    const float* fb = feat + (size_t)b * S * D;
    for (int i = t; i < TOPK * D; i += 512) {
        int k = i >> 9, d = i & (D - 1);
        os[i] = fb[(size_t)sel[k] * D + d];
    }
}

// ---------------------------------------------------------------------------
extern "C" void kernel_launch(void* const* d_in, const int* in_sizes, int n_in,
                              void* d_out, int out_size) {
    (void)in_sizes; (void)n_in; (void)out_size;
    const float* x  = (const float*)d_in[0];
    const float* w1 = (const float*)d_in[1];
    const float* b1 = (const float*)d_in[2];
    const float* w2 = (const float*)d_in[3];
    // d_in[4] = b2: constant shift, does not affect top-k ordering -> unused.

    float* out = (float*)d_out;
    float* feat = out + (size_t)B * TOPK * S + (size_t)B * TOPK * D;

    cudaFuncSetAttribute(k_gemm_mma, cudaFuncAttributeMaxDynamicSharedMemorySize, SMEM_GEMM);
    cudaFuncSetAttribute(k_spe_mma, cudaFuncAttributeMaxDynamicSharedMemorySize, SMEM_GEMM);

    k_mean<<<(B * D) / 8, 256>>>(x);
    k_transpose<<<dim3(S / 32, D / 32, B), dim3(32, 8)>>>(x, feat);
    k_w1t<<<dim3(16, 32), dim3(32, 8)>>>(w1);
    k_pe<<<(S * F) / 256, 256>>>();
    k_gproj<<<512, 256>>>(w1);
    k_spe_mma<<<128, 256, SMEM_GEMM>>>();
    k_spe_combine<<<(S * D) / 256, 256>>>(b1);
    k_gemm_mma<<<B * 4 * 4, 256, SMEM_GEMM>>>(w2);
    k_topk<<<B, 512>>>(out, feat);
}

// round 16
// speedup vs baseline: 2.0820x; 1.0951x over previous
#include <cuda_runtime.h>
#include <cuda_fp16.h>
#include <math.h>
#include <stdint.h>

// Problem dims
#define B 128
#define D 512
#define S 512
#define F 1024     // 2*D
#define TOPK 10

// scratch (device globals: allocation-free)
__device__ float g_info[B * D];
__device__ float g_gproj[B * D];
__device__ float g_spe[S * D];
__device__ float g_spe_part[8][S * D];
__device__ float g_part[4][B * S];   // partial scores per 128-col chunk

// fp16 2-way splits of feat (A), W1a^T / W1b^T (B, [d][f] k-contig), pe
__device__ __half g_as0[B * S * D];
__device__ __half g_as1[B * S * D];
__device__ __half g_w1t0[D * D];
__device__ __half g_w1t1[D * D];
__device__ __half g_w1bt0[D * D];
__device__ __half g_w1bt1[D * D];
__device__ __half g_pe0[S * F];
__device__ __half g_pe1[S * F];

// ---------------- helpers ----------------
__device__ __forceinline__ uint32_t smem_u32(const void* p) {
    uint32_t a;
    asm("{ .reg .u64 t; cvta.to.shared.u64 t, %1; cvt.u32.u64 %0, t; }" : "=r"(a) : "l"(p));
    return a;
}
#define CP_ASYNC16(dst, src) \
    asm volatile("cp.async.cg.shared.global [%0], [%1], 16;" :: "r"(dst), "l"(src))

#define LDSM4(r, addr) \
    asm volatile("ldmatrix.sync.aligned.m8n8.x4.shared.b16 {%0,%1,%2,%3}, [%4];" \
        : "=r"((r)[0]), "=r"((r)[1]), "=r"((r)[2]), "=r"((r)[3]) : "r"(addr))

#define MMA_FP16(d, a, b0r, b1r) \
    asm volatile("mma.sync.aligned.m16n8k16.row.col.f32.f16.f16.f32 " \
        "{%0,%1,%2,%3}, {%4,%5,%6,%7}, {%8,%9}, {%0,%1,%2,%3};" \
        : "+f"((d)[0]), "+f"((d)[1]), "+f"((d)[2]), "+f"((d)[3]) \
        : "r"((a)[0]), "r"((a)[1]), "r"((a)[2]), "r"((a)[3]), "r"(b0r), "r"(b1r))

// split fp32 -> 2 fp16 terms (captures ~22 bits; dropped a1*b1 term ~2^-22)
__device__ __forceinline__ void split2(float a, __half& h0, __half& h1) {
    h0 = __float2half_rn(a);
    float r1 = a - __half2float(h0);
    h1 = __float2half_rn(r1);
}

// ---------------------------------------------------------------------------
// Kernel 1: row means of x
__global__ void k_mean(const float* __restrict__ x) {
    int row = blockIdx.x * 8 + (threadIdx.x >> 5);
    int lane = threadIdx.x & 31;
    const float4* p = (const float4*)(x + (size_t)row * S);
    float s = 0.f;
    #pragma unroll
    for (int i = lane; i < S / 4; i += 32) {
        float4 v = p[i];
        s += v.x + v.y + v.z + v.w;
    }
    #pragma unroll
    for (int o = 16; o; o >>= 1) s += __shfl_xor_sync(0xffffffffu, s, o);
    if (lane == 0) g_info[row] = s * (1.0f / (float)S);
}

// ---------------------------------------------------------------------------
// Kernel 2: feat[b,s,d] = x[b,d,s]; also emit 2-way fp16 splits of feat
__global__ void k_transpose(const float* __restrict__ x, float* __restrict__ feat) {
    __shared__ float tile[32][33];
    int b = blockIdx.z;
    int d0 = blockIdx.y * 32, s0 = blockIdx.x * 32;
    const float* xb = x + (size_t)b * D * S;
    float* fb = feat + (size_t)b * S * D;
    int tx = threadIdx.x;
    #pragma unroll
    for (int i = threadIdx.y; i < 32; i += 8)
        tile[i][tx] = xb[(size_t)(d0 + i) * S + s0 + tx];
    __syncthreads();
    #pragma unroll
    for (int i = threadIdx.y; i < 32; i += 8) {
        float a = tile[tx][i];
        size_t o = (size_t)b * S * D + (size_t)(s0 + i) * D + d0 + tx;
        fb[(size_t)(s0 + i) * D + d0 + tx] = a;
        __half h0, h1;
        split2(a, h0, h1);
        g_as0[o] = h0; g_as1[o] = h1;
    }
}

// ---------------------------------------------------------------------------
// Kernel 2b: transpose+split all of w1: [d][f] for f<512 -> w1t, f>=512 -> w1bt
__global__ void k_w1t(const float* __restrict__ w1) {
    __shared__ float tile[32][33];
    int f0 = blockIdx.y * 32, d0 = blockIdx.x * 32;
    int tx = threadIdx.x;
    #pragma unroll
    for (int i = threadIdx.y; i < 32; i += 8)
        tile[i][tx] = w1[(size_t)(f0 + i) * D + d0 + tx];
    __syncthreads();
    int hi = (f0 >= 512);
    __half* o0 = hi ? g_w1bt0 : g_w1t0;
    __half* o1 = hi ? g_w1bt1 : g_w1t1;
    int fb = f0 - hi * 512;
    #pragma unroll
    for (int i = threadIdx.y; i < 32; i += 8) {
        float a = tile[tx][i];  // = w1[f0+tx][d0+i]
        size_t o = (size_t)(d0 + i) * D + fb + tx;
        __half h0, h1;
        split2(a, h0, h1);
        o0[o] = h0; o1[o] = h1;
    }
}

// ---------------------------------------------------------------------------
// Kernel 2c: pe[s][f] sinusoid, 2-way fp16 split
__global__ void k_pe() {
    int idx = blockIdx.x * 256 + threadIdx.x;
    int s = idx >> 10, f = idx & 1023;
    int fe = f & ~1;
    float div = expf(-9.210340371976184f * (float)fe / (float)F);
    float ang = (float)s * div;
    float v = (f & 1) ? cosf(ang) : sinf(ang);
    __half h0, h1;
    split2(v, h0, h1);
    g_pe0[idx] = h0; g_pe1[idx] = h1;
}

// ---------------------------------------------------------------------------
// Kernel 4: g_proj[b,d] = sum_f info_g[b,f] * w1[D+f, d]
__global__ void k_gproj(const float* __restrict__ w1) {
    __shared__ float info_s[D];
    __shared__ float part[128];
    int tid = threadIdx.x;
    int b = blockIdx.x >> 2, dq = blockIdx.x & 3;
    info_s[tid] = g_info[b * D + tid];
    info_s[tid + 256] = g_info[b * D + tid + 256];
    __syncthreads();
    int fg = tid >> 7, dc = tid & 127;
    int d = dq * 128 + dc;
    const float* wb = w1 + (size_t)D * D + d;
    int fb = fg * 256;
    float a0 = 0.f, a1 = 0.f, a2 = 0.f, a3 = 0.f;
    #pragma unroll 4
    for (int f = 0; f < 256; f += 4) {
        a0 += info_s[fb + f]     * wb[(size_t)(fb + f) * D];
        a1 += info_s[fb + f + 1] * wb[(size_t)(fb + f + 1) * D];
        a2 += info_s[fb + f + 2] * wb[(size_t)(fb + f + 2) * D];
        a3 += info_s[fb + f + 3] * wb[(size_t)(fb + f + 3) * D];
    }
    float s = (a0 + a1) + (a2 + a3);
    if (fg == 1) part[dc] = s;
    __syncthreads();
    if (fg == 0) g_gproj[b * D + d] = s + part[dc];
}

// ---------------------------------------------------------------------------
// Shared GEMM tile layout (pitch 80B, Kc=32, double buffered, 2 splits)
#define PITCH 10240                      // 128 rows * 80 B per (split) tile
#define ABUF(buf, sp) (((buf) * 2 + (sp)) * PITCH)
#define BBUF(buf, sp) (40960 + ((buf) * 2 + (sp)) * PITCH)
#define SMEM_GEMM 81920

// ---------------------------------------------------------------------------
// Kernel 3: spe via HMMA: spe_part[ks] = pe[:, ks*128:(ks+1)*128] @ W1[ks-chunk]
// grid = 8(ks) x 4(st) x 4(nc) = 128 blocks; per block K=128 (4 chunks of 32).
__global__ __launch_bounds__(256, 1) void k_spe_mma() {
    extern __shared__ __align__(16) char smem[];
    uint32_t sb = smem_u32(smem);
    int tid = threadIdx.x, wid = tid >> 5, lane = tid & 31;
    int ks = blockIdx.x >> 4;
    int st = (blockIdx.x >> 2) & 3;
    int nc = blockIdx.x & 3;
    int s0 = st * 128, n0 = nc * 128;
    int mw = wid & 1, nw = wid >> 1;

    const __half* apz[2] = {g_pe0, g_pe1};
    const __half* bpz[2];
    int f0base = ks * 128;
    int fob;
    if (ks < 4) { bpz[0] = g_w1t0;  bpz[1] = g_w1t1;  fob = f0base; }
    else        { bpz[0] = g_w1bt0; bpz[1] = g_w1bt1; fob = f0base - 512; }

    float acc[4][4][4];
    #pragma unroll
    for (int i = 0; i < 4; i++)
        #pragma unroll
        for (int j = 0; j < 4; j++)
            #pragma unroll
            for (int e = 0; e < 4; e++) acc[i][j][e] = 0.f;

#define SLOAD(fa, fb2, bufi) do {                                              \
    for (int t = tid; t < 1024; t += 256) {                                    \
        int sp = t >> 9; int rem = t & 511; int row = rem >> 2; int ck = rem & 3; \
        CP_ASYNC16(sb + ABUF(bufi, sp) + row * 80 + ck * 16,                   \
                   apz[sp] + (size_t)(s0 + row) * F + (fa) + ck * 8);          \
        CP_ASYNC16(sb + BBUF(bufi, sp) + row * 80 + ck * 16,                   \
                   bpz[sp] + (size_t)(n0 + row) * D + (fb2) + ck * 8);         \
    }                                                                          \
    asm volatile("cp.async.commit_group;");                                    \
} while (0)

    SLOAD(f0base, fob, 0);
    int buf = 0;
    for (int c = 0; c < 4; c++) {
        if (c < 3) {
            SLOAD(f0base + (c + 1) * 32, fob + (c + 1) * 32, buf ^ 1);
            asm volatile("cp.async.wait_group 1;");
        } else {
            asm volatile("cp.async.wait_group 0;");
        }
        __syncthreads();
        #pragma unroll
        for (int k16 = 0; k16 < 2; k16++) {
            uint32_t bfm[2][2][4];
            int brow = nw * 32 + ((lane >> 4) & 1) * 8 + (lane & 7);
            int bko = ((lane >> 3) & 1) * 16 + k16 * 32;
            #pragma unroll
            for (int sp = 0; sp < 2; sp++)
                #pragma unroll
                for (int q = 0; q < 2; q++)
                    LDSM4(bfm[sp][q], sb + BBUF(buf, sp) + (brow + q * 16) * 80 + bko);
            int amrow = mw * 64 + (lane & 15);
            int ako = (lane >> 4) * 16 + k16 * 32;
            #pragma unroll
            for (int i = 0; i < 2; i++) {
                uint32_t af[4][4];
                #pragma unroll
                for (int mt = 0; mt < 4; mt++)
                    LDSM4(af[mt], sb + ABUF(buf, i) + (amrow + mt * 16) * 80 + ako);
                #pragma unroll
                for (int j = 0; j < 2; j++) {
                    if (i == 1 && j == 1) continue;   // drop a1*b1 (~2^-22)
                    #pragma unroll
                    for (int mt = 0; mt < 4; mt++) {
                        MMA_FP16(acc[mt][0], af[mt], bfm[j][0][0], bfm[j][0][1]);
                        MMA_FP16(acc[mt][1], af[mt], bfm[j][0][2], bfm[j][0][3]);
                        MMA_FP16(acc[mt][2], af[mt], bfm[j][1][0], bfm[j][1][1]);
                        MMA_FP16(acc[mt][3], af[mt], bfm[j][1][2], bfm[j][1][3]);
                    }
                }
            }
        }
        __syncthreads();
        buf ^= 1;
    }

    // store partials (fp32)
    int g = lane >> 2, tig = lane & 3;
    float* outp = g_spe_part[ks];
    #pragma unroll
    for (int mt = 0; mt < 4; mt++) {
        int r0 = s0 + mw * 64 + mt * 16 + g;
        #pragma unroll
        for (int nt = 0; nt < 4; nt++) {
            int dcol = n0 + nw * 32 + nt * 8 + tig * 2;
            outp[(size_t)r0 * D + dcol]           = acc[mt][nt][0];
            outp[(size_t)r0 * D + dcol + 1]       = acc[mt][nt][1];
            outp[(size_t)(r0 + 8) * D + dcol]     = acc[mt][nt][2];
            outp[(size_t)(r0 + 8) * D + dcol + 1] = acc[mt][nt][3];
        }
    }
}

// ---------------------------------------------------------------------------
// Kernel 3b: spe = sum of 8 partials + b1
__global__ void k_spe_combine(const float* __restrict__ b1) {
    int idx = blockIdx.x * 256 + threadIdx.x;
    float s = 0.f;
    #pragma unroll
    for (int p = 0; p < 8; p++) s += g_spe_part[p][idx];
    g_spe[idx] = s + b1[idx & (D - 1)];
}

// ---------------------------------------------------------------------------
// Kernel 5: main fp16 mma.sync GEMM (2-split, 3 products), 2 CTAs/SM
__global__ __launch_bounds__(256, 2) void k_gemm_mma(const float* __restrict__ w2v) {
    extern __shared__ __align__(16) char smem[];
    uint32_t sb = smem_u32(smem);
    int tid = threadIdx.x, wid = tid >> 5, lane = tid & 31;
    int bidx = blockIdx.x >> 4;                 // batch
    int st = (blockIdx.x >> 2) & 3;             // s-tile (128 rows)
    int nc = blockIdx.x & 3;                    // n-chunk (128 cols)
    int s0 = st * 128, n0 = nc * 128;
    int mw = wid & 1, nw = wid >> 1;            // 2 x 4 warp grid

    const __half* aptr[2] = {g_as0, g_as1};
    const __half* bptr[2] = {g_w1t0, g_w1t1};
    size_t arow0 = (size_t)(bidx * S + s0);
    size_t brow0 = (size_t)n0;

    float acc[4][4][4];
    #pragma unroll
    for (int i = 0; i < 4; i++)
        #pragma unroll
        for (int j = 0; j < 4; j++)
            #pragma unroll
            for (int e = 0; e < 4; e++) acc[i][j][e] = 0.f;

#define LOAD_CHUNK(f0, bufi) do {                                              \
    for (int t = tid; t < 1024; t += 256) {                                    \
        int sp = t >> 9; int rem = t & 511; int row = rem >> 2; int ck = rem & 3; \
        CP_ASYNC16(sb + ABUF(bufi, sp) + row * 80 + ck * 16,                   \
                   aptr[sp] + (arow0 + row) * D + (f0) + ck * 8);              \
        CP_ASYNC16(sb + BBUF(bufi, sp) + row * 80 + ck * 16,                   \
                   bptr[sp] + (brow0 + row) * D + (f0) + ck * 8);              \
    }                                                                          \
    asm volatile("cp.async.commit_group;");                                    \
} while (0)

    LOAD_CHUNK(0, 0);
    int buf = 0;

    for (int c = 0; c < 16; c++) {
        if (c < 15) {
            LOAD_CHUNK((c + 1) * 32, buf ^ 1);
            asm volatile("cp.async.wait_group 1;");
        } else {
            asm volatile("cp.async.wait_group 0;");
        }
        __syncthreads();

        #pragma unroll
        for (int k16 = 0; k16 < 2; k16++) {
            uint32_t bf[2][2][4];
            int brow = nw * 32 + ((lane >> 4) & 1) * 8 + (lane & 7);
            int bko = ((lane >> 3) & 1) * 16 + k16 * 32;
            #pragma unroll
            for (int sp = 0; sp < 2; sp++)
                #pragma unroll
                for (int q = 0; q < 2; q++)
                    LDSM4(bf[sp][q], sb + BBUF(buf, sp) + (brow + q * 16) * 80 + bko);

            int amrow = mw * 64 + (lane & 15);
            int ako = (lane >> 4) * 16 + k16 * 32;
            #pragma unroll
            for (int i = 0; i < 2; i++) {
                uint32_t af[4][4];
                #pragma unroll
                for (int mt = 0; mt < 4; mt++)
                    LDSM4(af[mt], sb + ABUF(buf, i) + (amrow + mt * 16) * 80 + ako);
                #pragma unroll
                for (int j = 0; j < 2; j++) {
                    if (i == 1 && j == 1) continue;   // drop a1*b1 (~2^-22)
                    #pragma unroll
                    for (int mt = 0; mt < 4; mt++) {
                        MMA_FP16(acc[mt][0], af[mt], bf[j][0][0], bf[j][0][1]);
                        MMA_FP16(acc[mt][1], af[mt], bf[j][0][2], bf[j][0][3]);
                        MMA_FP16(acc[mt][2], af[mt], bf[j][1][0], bf[j][1][1]);
                        MMA_FP16(acc[mt][3], af[mt], bf[j][1][2], bf[j][1][3]);
                    }
                }
            }
        }
        __syncthreads();
        buf ^= 1;
    }

    // ---- epilogue: v += spe + gproj; relu; dot w2 -> partial scores ----
    float* scp = (float*)smem;
    int g = lane >> 2, tig = lane & 3;
    const float* gp = g_gproj + bidx * D;
    #pragma unroll
    for (int mt = 0; mt < 4; mt++) {
        int rl0 = mw * 64 + mt * 16 + g;
        int sg0 = s0 + rl0;
        float p0 = 0.f, p1 = 0.f;
        #pragma unroll
        for (int nt = 0; nt < 4; nt++) {
            #pragma unroll
            for (int e = 0; e < 2; e++) {
                int dcol = n0 + nw * 32 + nt * 8 + tig * 2 + e;
                float gpw = __ldg(&gp[dcol]);
                float wv  = __ldg(&w2v[dcol]);
                float v0 = acc[mt][nt][e]     + __ldg(&g_spe[(size_t)sg0 * D + dcol])       + gpw;
                float v1 = acc[mt][nt][2 + e] + __ldg(&g_spe[(size_t)(sg0 + 8) * D + dcol]) + gpw;
                if (v0 > 0.f) p0 += v0 * wv;
                if (v1 > 0.f) p1 += v1 * wv;
            }
        }
        p0 += __shfl_xor_sync(0xffffffffu, p0, 1);
        p0 += __shfl_xor_sync(0xffffffffu, p0, 2);
        p1 += __shfl_xor_sync(0xffffffffu, p1, 1);
        p1 += __shfl_xor_sync(0xffffffffu, p1, 2);
        if (tig == 0) {
            scp[rl0 * 4 + nw] = p0;
            scp[(rl0 + 8) * 4 + nw] = p1;
        }
    }
    __syncthreads();
    if (tid < 128)
        g_part[nc][bidx * S + s0 + tid] =
            (scp[tid * 4] + scp[tid * 4 + 1]) + (scp[tid * 4 + 2] + scp[tid * 4 + 3]);
}

// ---------------------------------------------------------------------------
// Kernel 6: sum partials, per-batch top-10, sort ascending, one-hot + gather.
__global__ void k_topk(float* __restrict__ out, const float* __restrict__ feat) {
    __shared__ float sv[S];
    __shared__ float rv[S];
    __shared__ int ri[S];
    __shared__ int sel[TOPK];
    int b = blockIdx.x;
    int t = threadIdx.x;
    int o = b * S + t;

    sv[t] = (g_part[0][o] + g_part[1][o]) + (g_part[2][o] + g_part[3][o]);

    for (int k = 0; k < TOPK; k++) {
        __syncthreads();
        rv[t] = sv[t];
        ri[t] = t;
        __syncthreads();
        for (int str = 256; str > 0; str >>= 1) {
            if (t < str) {
                float v2 = rv[t + str];
                int i2 = ri[t + str];
                if (v2 > rv[t] || (v2 == rv[t] && i2 < ri[t])) { rv[t] = v2; ri[t] = i2; }
            }
            __syncthreads();
        }
        if (t == 0) {
            sel[k] = ri[0];
            sv[ri[0]] = -INFINITY;
        }
    }
    __syncthreads();
    if (t == 0) {
        for (int i = 1; i < TOPK; i++) {
            int v = sel[i], j = i - 1;
            while (j >= 0 && sel[j] > v) { sel[j + 1] = sel[j]; j--; }
            sel[j + 1] = v;
        }
    }
    __syncthreads();

    float* oi = out + (size_t)b * TOPK * S;
    for (int i = t; i < TOPK * S; i += 512) {
        int k = i >> 9, s = i & (S - 1);
        oi[i] = (s == sel[k]) ? 1.0f : 0.0f;
    }
    float* os = out + (size_t)B * TOPK * S + (size_t)b * TOPK * D;
    const float* fb = feat + (size_t)b * S * D;
    for (int i = t; i < TOPK * D; i += 512) {
        int k = i >> 9, d = i & (D - 1);
        os[i] = fb[(size_t)sel[k] * D + d];
    }
}

// ---------------------------------------------------------------------------
extern "C" void kernel_launch(void* const* d_in, const int* in_sizes, int n_in,
                              void* d_out, int out_size) {
    (void)in_sizes; (void)n_in; (void)out_size;
    const float* x  = (const float*)d_in[0];
    const float* w1 = (const float*)d_in[1];
    const float* b1 = (const float*)d_in[2];
    const float* w2 = (const float*)d_in[3];
    // d_in[4] = b2: constant shift, does not affect top-k ordering -> unused.

    float* out = (float*)d_out;
    float* feat = out + (size_t)B * TOPK * S + (size_t)B * TOPK * D;

    cudaFuncSetAttribute(k_gemm_mma, cudaFuncAttributeMaxDynamicSharedMemorySize, SMEM_GEMM);
    cudaFuncSetAttribute(k_spe_mma, cudaFuncAttributeMaxDynamicSharedMemorySize, SMEM_GEMM);

    k_mean<<<(B * D) / 8, 256>>>(x);
    k_transpose<<<dim3(S / 32, D / 32, B), dim3(32, 8)>>>(x, feat);
    k_w1t<<<dim3(16, 32), dim3(32, 8)>>>(w1);
    k_pe<<<(S * F) / 256, 256>>>();
    k_gproj<<<512, 256>>>(w1);
    k_spe_mma<<<128, 256, SMEM_GEMM>>>();
    k_spe_combine<<<(S * D) / 256, 256>>>(b1);
    k_gemm_mma<<<B * 4 * 4, 256, SMEM_GEMM>>>(w2);
    k_topk<<<B, 512>>>(out, feat);
}

// round 17
// speedup vs baseline: 2.2957x; 1.1026x over previous
#include <cuda_runtime.h>
#include <cuda_fp16.h>
#include <math.h>
#include <stdint.h>

// Problem dims
#define B 128
#define D 512
#define S 512
#define F 1024     // 2*D
#define TOPK 10

// scratch (device globals: allocation-free)
__device__ float g_info[B * D];
__device__ float g_gproj[B * D];
__device__ float g_spe[S * D];
__device__ float g_spe_part[8][S * D];
__device__ float g_part[4][B * S];   // partial scores per 128-col chunk

// fp16 2-way splits of feat (A), W1a^T / W1b^T (B, [d][f] k-contig), pe
__device__ __half g_as0[B * S * D];
__device__ __half g_as1[B * S * D];
__device__ __half g_w1t0[D * D];
__device__ __half g_w1t1[D * D];
__device__ __half g_w1bt0[D * D];
__device__ __half g_w1bt1[D * D];
__device__ __half g_pe0[S * F];
__device__ __half g_pe1[S * F];

// ---------------- helpers ----------------
__device__ __forceinline__ uint32_t smem_u32(const void* p) {
    uint32_t a;
    asm("{ .reg .u64 t; cvta.to.shared.u64 t, %1; cvt.u32.u64 %0, t; }" : "=r"(a) : "l"(p));
    return a;
}
#define CP_ASYNC16(dst, src) \
    asm volatile("cp.async.cg.shared.global [%0], [%1], 16;" :: "r"(dst), "l"(src))

#define LDSM4(r, addr) \
    asm volatile("ldmatrix.sync.aligned.m8n8.x4.shared.b16 {%0,%1,%2,%3}, [%4];" \
        : "=r"((r)[0]), "=r"((r)[1]), "=r"((r)[2]), "=r"((r)[3]) : "r"(addr))

#define MMA_FP16(d, a, b0r, b1r) \
    asm volatile("mma.sync.aligned.m16n8k16.row.col.f32.f16.f16.f32 " \
        "{%0,%1,%2,%3}, {%4,%5,%6,%7}, {%8,%9}, {%0,%1,%2,%3};" \
        : "+f"((d)[0]), "+f"((d)[1]), "+f"((d)[2]), "+f"((d)[3]) \
        : "r"((a)[0]), "r"((a)[1]), "r"((a)[2]), "r"((a)[3]), "r"(b0r), "r"(b1r))

// split fp32 -> 2 fp16 terms (captures ~22 bits; dropped a1*b1 term ~2^-22)
__device__ __forceinline__ void split2(float a, __half& h0, __half& h1) {
    h0 = __float2half_rn(a);
    float r1 = a - __half2float(h0);
    h1 = __float2half_rn(r1);
}

// ---------------------------------------------------------------------------
// Kernel 2 (fused): feat[b,s,d] = x[b,d,s], fp16 splits, AND row means.
// One block = (b, 64-d strip) across ALL s -> means accumulate in registers.
__global__ __launch_bounds__(256) void k_trans(const float* __restrict__ x,
                                               float* __restrict__ feat) {
    __shared__ float tile[64][33];
    int b = blockIdx.y, d0 = blockIdx.x * 64;
    int tid = threadIdx.x;
    int lane = tid & 31, w = tid >> 5;   // 8 warps
    const float* xb = x + (size_t)b * D * S;
    float* fb = feat + (size_t)b * S * D;
    float msum[8] = {0.f, 0.f, 0.f, 0.f, 0.f, 0.f, 0.f, 0.f};

    for (int st = 0; st < 16; st++) {
        int s0 = st * 32;
        __syncthreads();
        // load 64 x 32 (coalesced along s)
        #pragma unroll
        for (int r = w; r < 64; r += 8)
            tile[r][lane] = xb[(size_t)(d0 + r) * S + s0 + lane];
        __syncthreads();
        // mean accumulation: warp w owns d-rows 8w..8w+7
        #pragma unroll
        for (int r = 0; r < 8; r++)
            msum[r] += tile[w * 8 + r][lane];
        // write: warp w handles s-rows w, w+8, w+16, w+24; lane -> 2 consecutive d
        #pragma unroll
        for (int i = w; i < 32; i += 8) {
            int s = s0 + i;
            float v0 = tile[lane * 2][i];
            float v1 = tile[lane * 2 + 1][i];
            size_t o = (size_t)b * S * D + (size_t)s * D + d0 + lane * 2;
            *(float2*)&fb[(size_t)s * D + d0 + lane * 2] = make_float2(v0, v1);
            __half h00, h01, h10, h11;
            split2(v0, h00, h01);
            split2(v1, h10, h11);
            *(__half2*)&g_as0[o] = __halves2half2(h00, h10);
            *(__half2*)&g_as1[o] = __halves2half2(h01, h11);
        }
    }
    // finalize means
    #pragma unroll
    for (int r = 0; r < 8; r++) {
        float s = msum[r];
        #pragma unroll
        for (int o = 16; o; o >>= 1) s += __shfl_xor_sync(0xffffffffu, s, o);
        if (lane == 0) g_info[b * D + d0 + w * 8 + r] = s * (1.0f / (float)S);
    }
}

// ---------------------------------------------------------------------------
// Kernel 2b: transpose+split all of w1: [d][f] for f<512 -> w1t, f>=512 -> w1bt
__global__ void k_w1t(const float* __restrict__ w1) {
    __shared__ float tile[32][33];
    int f0 = blockIdx.y * 32, d0 = blockIdx.x * 32;
    int tx = threadIdx.x;
    #pragma unroll
    for (int i = threadIdx.y; i < 32; i += 8)
        tile[i][tx] = w1[(size_t)(f0 + i) * D + d0 + tx];
    __syncthreads();
    int hi = (f0 >= 512);
    __half* o0 = hi ? g_w1bt0 : g_w1t0;
    __half* o1 = hi ? g_w1bt1 : g_w1t1;
    int fb = f0 - hi * 512;
    #pragma unroll
    for (int i = threadIdx.y; i < 32; i += 8) {
        float a = tile[tx][i];  // = w1[f0+tx][d0+i]
        size_t o = (size_t)(d0 + i) * D + fb + tx;
        __half h0, h1;
        split2(a, h0, h1);
        o0[o] = h0; o1[o] = h1;
    }
}

// ---------------------------------------------------------------------------
// Kernel 2c: pe[s][f] sinusoid, 2-way fp16 split
__global__ void k_pe() {
    int idx = blockIdx.x * 256 + threadIdx.x;
    int s = idx >> 10, f = idx & 1023;
    int fe = f & ~1;
    float div = expf(-9.210340371976184f * (float)fe / (float)F);
    float ang = (float)s * div;
    float v = (f & 1) ? cosf(ang) : sinf(ang);
    __half h0, h1;
    split2(v, h0, h1);
    g_pe0[idx] = h0; g_pe1[idx] = h1;
}

// ---------------------------------------------------------------------------
// Kernel 4: g_proj[b,d] = sum_f info_g[b,f] * w1[D+f, d]
__global__ void k_gproj(const float* __restrict__ w1) {
    __shared__ float info_s[D];
    __shared__ float part[128];
    int tid = threadIdx.x;
    int b = blockIdx.x >> 2, dq = blockIdx.x & 3;
    info_s[tid] = g_info[b * D + tid];
    info_s[tid + 256] = g_info[b * D + tid + 256];
    __syncthreads();
    int fg = tid >> 7, dc = tid & 127;
    int d = dq * 128 + dc;
    const float* wb = w1 + (size_t)D * D + d;
    int fb = fg * 256;
    float a0 = 0.f, a1 = 0.f, a2 = 0.f, a3 = 0.f;
    #pragma unroll 4
    for (int f = 0; f < 256; f += 4) {
        a0 += info_s[fb + f]     * wb[(size_t)(fb + f) * D];
        a1 += info_s[fb + f + 1] * wb[(size_t)(fb + f + 1) * D];
        a2 += info_s[fb + f + 2] * wb[(size_t)(fb + f + 2) * D];
        a3 += info_s[fb + f + 3] * wb[(size_t)(fb + f + 3) * D];
    }
    float s = (a0 + a1) + (a2 + a3);
    if (fg == 1) part[dc] = s;
    __syncthreads();
    if (fg == 0) g_gproj[b * D + d] = s + part[dc];
}

// ---------------------------------------------------------------------------
// Shared GEMM tile layout (pitch 80B, Kc=32, double buffered, 2 splits)
#define PITCH 10240                      // 128 rows * 80 B per (split) tile
#define ABUF(buf, sp) (((buf) * 2 + (sp)) * PITCH)
#define BBUF(buf, sp) (40960 + ((buf) * 2 + (sp)) * PITCH)
#define SMEM_GEMM 81920

// ---------------------------------------------------------------------------
// Kernel 3: spe via HMMA: spe_part[ks] = pe[:, ks*128:(ks+1)*128] @ W1[ks-chunk]
__global__ __launch_bounds__(256, 1) void k_spe_mma() {
    extern __shared__ __align__(16) char smem[];
    uint32_t sb = smem_u32(smem);
    int tid = threadIdx.x, wid = tid >> 5, lane = tid & 31;
    int ks = blockIdx.x >> 4;
    int st = (blockIdx.x >> 2) & 3;
    int nc = blockIdx.x & 3;
    int s0 = st * 128, n0 = nc * 128;
    int mw = wid & 1, nw = wid >> 1;

    const __half* apz[2] = {g_pe0, g_pe1};
    const __half* bpz[2];
    int f0base = ks * 128;
    int fob;
    if (ks < 4) { bpz[0] = g_w1t0;  bpz[1] = g_w1t1;  fob = f0base; }
    else        { bpz[0] = g_w1bt0; bpz[1] = g_w1bt1; fob = f0base - 512; }

    float acc[4][4][4];
    #pragma unroll
    for (int i = 0; i < 4; i++)
        #pragma unroll
        for (int j = 0; j < 4; j++)
            #pragma unroll
            for (int e = 0; e < 4; e++) acc[i][j][e] = 0.f;

#define SLOAD(fa, fb2, bufi) do {                                              \
    for (int t = tid; t < 1024; t += 256) {                                    \
        int sp = t >> 9; int rem = t & 511; int row = rem >> 2; int ck = rem & 3; \
        CP_ASYNC16(sb + ABUF(bufi, sp) + row * 80 + ck * 16,                   \
                   apz[sp] + (size_t)(s0 + row) * F + (fa) + ck * 8);          \
        CP_ASYNC16(sb + BBUF(bufi, sp) + row * 80 + ck * 16,                   \
                   bpz[sp] + (size_t)(n0 + row) * D + (fb2) + ck * 8);         \
    }                                                                          \
    asm volatile("cp.async.commit_group;");                                    \
} while (0)

    SLOAD(f0base, fob, 0);
    int buf = 0;
    for (int c = 0; c < 4; c++) {
        if (c < 3) {
            SLOAD(f0base + (c + 1) * 32, fob + (c + 1) * 32, buf ^ 1);
            asm volatile("cp.async.wait_group 1;");
        } else {
            asm volatile("cp.async.wait_group 0;");
        }
        __syncthreads();
        #pragma unroll
        for (int k16 = 0; k16 < 2; k16++) {
            uint32_t bfm[2][2][4];
            int brow = nw * 32 + ((lane >> 4) & 1) * 8 + (lane & 7);
            int bko = ((lane >> 3) & 1) * 16 + k16 * 32;
            #pragma unroll
            for (int sp = 0; sp < 2; sp++)
                #pragma unroll
                for (int q = 0; q < 2; q++)
                    LDSM4(bfm[sp][q], sb + BBUF(buf, sp) + (brow + q * 16) * 80 + bko);
            int amrow = mw * 64 + (lane & 15);
            int ako = (lane >> 4) * 16 + k16 * 32;
            #pragma unroll
            for (int i = 0; i < 2; i++) {
                uint32_t af[4][4];
                #pragma unroll
                for (int mt = 0; mt < 4; mt++)
                    LDSM4(af[mt], sb + ABUF(buf, i) + (amrow + mt * 16) * 80 + ako);
                #pragma unroll
                for (int j = 0; j < 2; j++) {
                    if (i == 1 && j == 1) continue;   // drop a1*b1 (~2^-22)
                    #pragma unroll
                    for (int mt = 0; mt < 4; mt++) {
                        MMA_FP16(acc[mt][0], af[mt], bfm[j][0][0], bfm[j][0][1]);
                        MMA_FP16(acc[mt][1], af[mt], bfm[j][0][2], bfm[j][0][3]);
                        MMA_FP16(acc[mt][2], af[mt], bfm[j][1][0], bfm[j][1][1]);
                        MMA_FP16(acc[mt][3], af[mt], bfm[j][1][2], bfm[j][1][3]);
                    }
                }
            }
        }
        __syncthreads();
        buf ^= 1;
    }

    // store partials (fp32)
    int g = lane >> 2, tig = lane & 3;
    float* outp = g_spe_part[ks];
    #pragma unroll
    for (int mt = 0; mt < 4; mt++) {
        int r0 = s0 + mw * 64 + mt * 16 + g;
        #pragma unroll
        for (int nt = 0; nt < 4; nt++) {
            int dcol = n0 + nw * 32 + nt * 8 + tig * 2;
            outp[(size_t)r0 * D + dcol]           = acc[mt][nt][0];
            outp[(size_t)r0 * D + dcol + 1]       = acc[mt][nt][1];
            outp[(size_t)(r0 + 8) * D + dcol]     = acc[mt][nt][2];
            outp[(size_t)(r0 + 8) * D + dcol + 1] = acc[mt][nt][3];
        }
    }
}

// ---------------------------------------------------------------------------
// Kernel 3b: spe = sum of 8 partials + b1
__global__ void k_spe_combine(const float* __restrict__ b1) {
    int idx = blockIdx.x * 256 + threadIdx.x;
    float s = 0.f;
    #pragma unroll
    for (int p = 0; p < 8; p++) s += g_spe_part[p][idx];
    g_spe[idx] = s + b1[idx & (D - 1)];
}

// ---------------------------------------------------------------------------
// Kernel 5: main fp16 mma.sync GEMM (2-split, 3 products), 2 CTAs/SM
__global__ __launch_bounds__(256, 2) void k_gemm_mma(const float* __restrict__ w2v) {
    extern __shared__ __align__(16) char smem[];
    uint32_t sb = smem_u32(smem);
    int tid = threadIdx.x, wid = tid >> 5, lane = tid & 31;
    int bidx = blockIdx.x >> 4;                 // batch
    int st = (blockIdx.x >> 2) & 3;             // s-tile (128 rows)
    int nc = blockIdx.x & 3;                    // n-chunk (128 cols)
    int s0 = st * 128, n0 = nc * 128;
    int mw = wid & 1, nw = wid >> 1;            // 2 x 4 warp grid

    const __half* aptr[2] = {g_as0, g_as1};
    const __half* bptr[2] = {g_w1t0, g_w1t1};
    size_t arow0 = (size_t)(bidx * S + s0);
    size_t brow0 = (size_t)n0;

    float acc[4][4][4];
    #pragma unroll
    for (int i = 0; i < 4; i++)
        #pragma unroll
        for (int j = 0; j < 4; j++)
            #pragma unroll
            for (int e = 0; e < 4; e++) acc[i][j][e] = 0.f;

#define LOAD_CHUNK(f0, bufi) do {                                              \
    for (int t = tid; t < 1024; t += 256) {                                    \
        int sp = t >> 9; int rem = t & 511; int row = rem >> 2; int ck = rem & 3; \
        CP_ASYNC16(sb + ABUF(bufi, sp) + row * 80 + ck * 16,                   \
                   aptr[sp] + (arow0 + row) * D + (f0) + ck * 8);              \
        CP_ASYNC16(sb + BBUF(bufi, sp) + row * 80 + ck * 16,                   \
                   bptr[sp] + (brow0 + row) * D + (f0) + ck * 8);              \
    }                                                                          \
    asm volatile("cp.async.commit_group;");                                    \
} while (0)

    LOAD_CHUNK(0, 0);
    int buf = 0;

    for (int c = 0; c < 16; c++) {
        if (c < 15) {
            LOAD_CHUNK((c + 1) * 32, buf ^ 1);
            asm volatile("cp.async.wait_group 1;");
        } else {
            asm volatile("cp.async.wait_group 0;");
        }
        __syncthreads();

        #pragma unroll
        for (int k16 = 0; k16 < 2; k16++) {
            uint32_t bf[2][2][4];
            int brow = nw * 32 + ((lane >> 4) & 1) * 8 + (lane & 7);
            int bko = ((lane >> 3) & 1) * 16 + k16 * 32;
            #pragma unroll
            for (int sp = 0; sp < 2; sp++)
                #pragma unroll
                for (int q = 0; q < 2; q++)
                    LDSM4(bf[sp][q], sb + BBUF(buf, sp) + (brow + q * 16) * 80 + bko);

            int amrow = mw * 64 + (lane & 15);
            int ako = (lane >> 4) * 16 + k16 * 32;
            #pragma unroll
            for (int i = 0; i < 2; i++) {
                uint32_t af[4][4];
                #pragma unroll
                for (int mt = 0; mt < 4; mt++)
                    LDSM4(af[mt], sb + ABUF(buf, i) + (amrow + mt * 16) * 80 + ako);
                #pragma unroll
                for (int j = 0; j < 2; j++) {
                    if (i == 1 && j == 1) continue;   // drop a1*b1 (~2^-22)
                    #pragma unroll
                    for (int mt = 0; mt < 4; mt++) {
                        MMA_FP16(acc[mt][0], af[mt], bf[j][0][0], bf[j][0][1]);
                        MMA_FP16(acc[mt][1], af[mt], bf[j][0][2], bf[j][0][3]);
                        MMA_FP16(acc[mt][2], af[mt], bf[j][1][0], bf[j][1][1]);
                        MMA_FP16(acc[mt][3], af[mt], bf[j][1][2], bf[j][1][3]);
                    }
                }
            }
        }
        __syncthreads();
        buf ^= 1;
    }

    // ---- epilogue: v += spe + gproj; relu; dot w2 -> partial scores ----
    float* scp = (float*)smem;
    int g = lane >> 2, tig = lane & 3;
    const float* gp = g_gproj + bidx * D;
    #pragma unroll
    for (int mt = 0; mt < 4; mt++) {
        int rl0 = mw * 64 + mt * 16 + g;
        int sg0 = s0 + rl0;
        float p0 = 0.f, p1 = 0.f;
        #pragma unroll
        for (int nt = 0; nt < 4; nt++) {
            #pragma unroll
            for (int e = 0; e < 2; e++) {
                int dcol = n0 + nw * 32 + nt * 8 + tig * 2 + e;
                float gpw = __ldg(&gp[dcol]);
                float wv  = __ldg(&w2v[dcol]);
                float v0 = acc[mt][nt][e]     + __ldg(&g_spe[(size_t)sg0 * D + dcol])       + gpw;
                float v1 = acc[mt][nt][2 + e] + __ldg(&g_spe[(size_t)(sg0 + 8) * D + dcol]) + gpw;
                if (v0 > 0.f) p0 += v0 * wv;
                if (v1 > 0.f) p1 += v1 * wv;
            }
        }
        p0 += __shfl_xor_sync(0xffffffffu, p0, 1);
        p0 += __shfl_xor_sync(0xffffffffu, p0, 2);
        p1 += __shfl_xor_sync(0xffffffffu, p1, 1);
        p1 += __shfl_xor_sync(0xffffffffu, p1, 2);
        if (tig == 0) {
            scp[rl0 * 4 + nw] = p0;
            scp[(rl0 + 8) * 4 + nw] = p1;
        }
    }
    __syncthreads();
    if (tid < 128)
        g_part[nc][bidx * S + s0 + tid] =
            (scp[tid * 4] + scp[tid * 4 + 1]) + (scp[tid * 4 + 2] + scp[tid * 4 + 3]);
}

// ---------------------------------------------------------------------------
// Kernel 6: sum partials, per-batch top-10 via warp shuffles, sort, emit.
__global__ void k_topk(float* __restrict__ out, const float* __restrict__ feat) {
    __shared__ float sv[S];
    __shared__ float wv[16];
    __shared__ int wi[16];
    __shared__ int sel[TOPK];
    int b = blockIdx.x;
    int t = threadIdx.x;   // 512
    int lane = t & 31, w = t >> 5;
    int o = b * S + t;

    sv[t] = (g_part[0][o] + g_part[1][o]) + (g_part[2][o] + g_part[3][o]);
    __syncthreads();

    for (int k = 0; k < TOPK; k++) {
        float v = sv[t];
        int idx = t;
        #pragma unroll
        for (int of = 16; of; of >>= 1) {
            float v2 = __shfl_xor_sync(0xffffffffu, v, of);
            int i2 = __shfl_xor_sync(0xffffffffu, idx, of);
            if (v2 > v || (v2 == v && i2 < idx)) { v = v2; idx = i2; }
        }
        if (lane == 0) { wv[w] = v; wi[w] = idx; }
        __syncthreads();
        if (w == 0) {
            float vv = (lane < 16) ? wv[lane] : -INFINITY;
            int ii = (lane < 16) ? wi[lane] : 0x7fffffff;
            #pragma unroll
            for (int of = 8; of; of >>= 1) {
                float v2 = __shfl_xor_sync(0xffffffffu, vv, of);
                int i2 = __shfl_xor_sync(0xffffffffu, ii, of);
                if (v2 > vv || (v2 == vv && i2 < ii)) { vv = v2; ii = i2; }
            }
            if (lane == 0) {
                sel[k] = ii;
                sv[ii] = -INFINITY;
            }
        }
        __syncthreads();
    }
    if (t == 0) {
        for (int i = 1; i < TOPK; i++) {
            int v = sel[i], j = i - 1;
            while (j >= 0 && sel[j] > v) { sel[j + 1] = sel[j]; j--; }
            sel[j + 1] = v;
        }
    }
    __syncthreads();

    float* oi = out + (size_t)b * TOPK * S;
    for (int i = t; i < TOPK * S; i += 512) {
        int k = i >> 9, s = i & (S - 1);
        oi[i] = (s == sel[k]) ? 1.0f : 0.0f;
    }
    float* os = out + (size_t)B * TOPK * S + (size_t)b * TOPK * D;
    const float* fb = feat + (size_t)b * S * D;
    for (int i = t; i < TOPK * D; i += 512) {
        int k = i >> 9, d = i & (D - 1);
        os[i] = fb[(size_t)sel[k] * D + d];
    }
}

// ---------------------------------------------------------------------------
extern "C" void kernel_launch(void* const* d_in, const int* in_sizes, int n_in,
                              void* d_out, int out_size) {
    (void)in_sizes; (void)n_in; (void)out_size;
    const float* x  = (const float*)d_in[0];
    const float* w1 = (const float*)d_in[1];
    const float* b1 = (const float*)d_in[2];
    const float* w2 = (const float*)d_in[3];
    // d_in[4] = b2: constant shift, does not affect top-k ordering -> unused.

    float* out = (float*)d_out;
    float* feat = out + (size_t)B * TOPK * S + (size_t)B * TOPK * D;

    cudaFuncSetAttribute(k_gemm_mma, cudaFuncAttributeMaxDynamicSharedMemorySize, SMEM_GEMM);
    cudaFuncSetAttribute(k_spe_mma, cudaFuncAttributeMaxDynamicSharedMemorySize, SMEM_GEMM);

    k_trans<<<dim3(D / 64, B), 256>>>(x, feat);
    k_w1t<<<dim3(16, 32), dim3(32, 8)>>>(w1);
    k_pe<<<(S * F) / 256, 256>>>();
    k_gproj<<<512, 256>>>(w1);
    k_spe_mma<<<128, 256, SMEM_GEMM>>>();
    k_spe_combine<<<(S * D) / 256, 256>>>(b1);
    k_gemm_mma<<<B * 4 * 4, 256, SMEM_GEMM>>>(w2);
    k_topk<<<B, 512>>>(out, feat);
}